// round 5
// baseline (speedup 1.0000x reference)
#include <cuda_runtime.h>
#include <math.h>

// Problem dims
#define Bsz  128
#define Nn   1024
#define Dd   256
#define Gg   64
#define GSZc 3
#define RELD 16
#define KDc  64
#define PDc  64
#define NFc  64
#define Qq   (Gg * GSZc)          // 192

// ---------------- scratch (static device globals; no allocation) ------------
__device__ float g_pe[Nn * KDc];                     // PE table
__device__ float g_fsym[NFc * GSZc * GSZc * RELD];   // symmetrized filters
__device__ float g_wt[Dd * 2 * RELD * PDc];          // 256x2048 Wq|Wk transposed
__device__ float g_k[Bsz * Nn * KDc];                // keys
__device__ float g_sc[Bsz * Qq * Nn];                // logits/scores
__device__ float g_gobj[Bsz * Qq * Dd];              // attended objects
__device__ float g_zz[(long)Bsz * Qq * 2048];        // zq|zk

// ---------------- small precompute kernels ----------------------------------

__global__ void pe_kernel() {
    int idx = blockIdx.x * blockDim.x + threadIdx.x;
    if (idx >= Nn * KDc) return;
    int n = idx >> 6, j = idx & 63;
    float e = (float)(j & ~1) / 64.0f;
    float denom = powf(10000.0f, e);
    float angle = (float)n / denom;
    double a = (double)angle;
    g_pe[idx] = (j & 1) ? (float)cos(a) : (float)sin(a);
}

// Fsym[f,n,m,r] = (1/6) sum over 6 permutations sigma of F[f,sigma(n),sigma(m),r]
__global__ void fsym_kernel(const float* __restrict__ filters) {
    int idx = blockIdx.x * blockDim.x + threadIdx.x;
    if (idx >= NFc * 144) return;
    int f = idx / 144, rem = idx % 144;
    int n = rem / 48, m = (rem / 16) % 3, r = rem & 15;
    const int P[6][3] = {{0,1,2},{0,2,1},{1,0,2},{1,2,0},{2,0,1},{2,1,0}};
    float s = 0.f;
#pragma unroll
    for (int p = 0; p < 6; p++)
        s += filters[f * 144 + P[p][n] * 48 + P[p][m] * 16 + r];
    g_fsym[idx] = s * (1.0f / 6.0f);
}

__global__ void wtrans_kernel(const float* __restrict__ Wq,
                              const float* __restrict__ Wk) {
    int idx = blockIdx.x * blockDim.x + threadIdx.x;
    if (idx >= Dd * 2048) return;
    int d = idx >> 11, c = idx & 2047;
    const float* W = (c < 1024) ? Wq : Wk;
    int cc = c & 1023;
    int r = cc >> 6, p = cc & 63;
    g_wt[idx] = W[(r << 14) + (d << 6) + p];
}

// ---------------- high-throughput tiled SGEMM --------------------------------
// BK=8, 8x8 microtile (split 4+4 fragments for conflict-free LDS.128),
// double-buffered smem with register prefetch.
// TRANSB: B given as (N x K) row-major, computes A @ B^T.
template<int BM, int BN, int THREADS, bool TRANSB, bool ADD_PE>
__global__ __launch_bounds__(THREADS)
void gemm_tile(const float* __restrict__ A, const float* __restrict__ B,
               float* __restrict__ C, int M, int N, int K,
               long sA, long sB, long sC, float alpha) {
    constexpr int TX = BN / 8;
    constexpr int SA = BM + 4;
    constexpr int SB = TRANSB ? (BN + 4) : BN;
    constexpr int NA = 2 * BM / THREADS;   // float4 chunks of A per thread
    constexpr int NB = 2 * BN / THREADS;   // float4 chunks of B per thread
    static_assert(TX * (BM / 8) == THREADS, "thread grid");
    __shared__ __align__(16) float As[2][8][SA];
    __shared__ __align__(16) float Bs[2][8][SB];

    A += (long)blockIdx.z * sA;
    B += (long)blockIdx.z * sB;
    C += (long)blockIdx.z * sC;
    const int m0 = blockIdx.y * BM;
    const int n0 = blockIdx.x * BN;
    const int t = threadIdx.x;
    const int tx = t % TX, ty = t / TX;

    float4 ra[NA], rb[NB];

    auto ldg = [&](int k0) {
#pragma unroll
        for (int i = 0; i < NA; i++) {
            int g = t + i * THREADS;
            int row = g >> 1, kc = (g & 1) << 2;
            ra[i] = *(const float4*)&A[(long)(m0 + row) * K + k0 + kc];
        }
#pragma unroll
        for (int i = 0; i < NB; i++) {
            int g = t + i * THREADS;
            if (TRANSB) {
                int row = g >> 1, kc = (g & 1) << 2;
                rb[i] = *(const float4*)&B[(long)(n0 + row) * K + k0 + kc];
            } else {
                int kr = g / (BN / 4), col = (g % (BN / 4)) << 2;
                rb[i] = *(const float4*)&B[(long)(k0 + kr) * N + n0 + col];
            }
        }
    };
    auto sts = [&](int buf) {
#pragma unroll
        for (int i = 0; i < NA; i++) {
            int g = t + i * THREADS;
            int row = g >> 1, kc = (g & 1) << 2;
            As[buf][kc + 0][row] = ra[i].x;
            As[buf][kc + 1][row] = ra[i].y;
            As[buf][kc + 2][row] = ra[i].z;
            As[buf][kc + 3][row] = ra[i].w;
        }
#pragma unroll
        for (int i = 0; i < NB; i++) {
            int g = t + i * THREADS;
            if (TRANSB) {
                int row = g >> 1, kc = (g & 1) << 2;
                Bs[buf][kc + 0][row] = rb[i].x;
                Bs[buf][kc + 1][row] = rb[i].y;
                Bs[buf][kc + 2][row] = rb[i].z;
                Bs[buf][kc + 3][row] = rb[i].w;
            } else {
                int kr = g / (BN / 4), col = (g % (BN / 4)) << 2;
                *(float4*)&Bs[buf][kr][col] = rb[i];
            }
        }
    };

    float acc[8][8] = {};
    ldg(0);
    sts(0);
    __syncthreads();
    const int KT = K / 8;
    for (int kt = 0; kt < KT; kt++) {
        if (kt + 1 < KT) ldg((kt + 1) * 8);
        const int buf = kt & 1;
#pragma unroll
        for (int kk = 0; kk < 8; kk++) {
            float4 a0 = *(const float4*)&As[buf][kk][ty * 4];
            float4 a1 = *(const float4*)&As[buf][kk][BM / 2 + ty * 4];
            float4 b0 = *(const float4*)&Bs[buf][kk][tx * 4];
            float4 b1 = *(const float4*)&Bs[buf][kk][BN / 2 + tx * 4];
            float ar[8] = {a0.x, a0.y, a0.z, a0.w, a1.x, a1.y, a1.z, a1.w};
            float br[8] = {b0.x, b0.y, b0.z, b0.w, b1.x, b1.y, b1.z, b1.w};
#pragma unroll
            for (int i = 0; i < 8; i++)
#pragma unroll
                for (int j = 0; j < 8; j++) acc[i][j] += ar[i] * br[j];
        }
        if (kt + 1 < KT) {
            sts(buf ^ 1);
            __syncthreads();
        }
    }

#pragma unroll
    for (int i = 0; i < 8; i++) {
        int row = m0 + ((i < 4) ? (ty * 4 + i) : (BM / 2 + ty * 4 + i - 4));
#pragma unroll
        for (int jh = 0; jh < 2; jh++) {
            int col = n0 + (jh ? (BN / 2 + tx * 4) : (tx * 4));
            float4 o;
            o.x = acc[i][jh * 4 + 0] * alpha;
            o.y = acc[i][jh * 4 + 1] * alpha;
            o.z = acc[i][jh * 4 + 2] * alpha;
            o.w = acc[i][jh * 4 + 3] * alpha;
            if (ADD_PE) {
                const float* pe = &g_pe[(row & (Nn - 1)) * 64 + col];
                o.x += pe[0]; o.y += pe[1]; o.z += pe[2]; o.w += pe[3];
            }
            *(float4*)&C[(long)row * N + col] = o;
        }
    }
}

// ---------------- row softmax over 1024, in place ----------------------------
__global__ __launch_bounds__(256)
void softmax_kernel(float* __restrict__ data) {
    __shared__ float red_m[8], red_s[8];
    float* p = data + (long)blockIdx.x * 1024;
    int t = threadIdx.x;
    float4 v = ((float4*)p)[t];
    float m = fmaxf(fmaxf(v.x, v.y), fmaxf(v.z, v.w));
#pragma unroll
    for (int o = 16; o; o >>= 1) m = fmaxf(m, __shfl_xor_sync(0xffffffffu, m, o));
    if ((t & 31) == 0) red_m[t >> 5] = m;
    __syncthreads();
    float bm = red_m[0];
#pragma unroll
    for (int i = 1; i < 8; i++) bm = fmaxf(bm, red_m[i]);
    v.x = expf(v.x - bm); v.y = expf(v.y - bm);
    v.z = expf(v.z - bm); v.w = expf(v.w - bm);
    float s = v.x + v.y + v.z + v.w;
#pragma unroll
    for (int o = 16; o; o >>= 1) s += __shfl_xor_sync(0xffffffffu, s, o);
    if ((t & 31) == 0) red_s[t >> 5] = s;
    __syncthreads();
    float tot = red_s[0];
#pragma unroll
    for (int i = 1; i < 8; i++) tot += red_s[i];
    float inv = 1.0f / tot;
    v.x *= inv; v.y *= inv; v.z *= inv; v.w *= inv;
    ((float4*)p)[t] = v;
}

// ---------------- final: R[n,m,r] then contract with Fsym --------------------
__global__ __launch_bounds__(288)
void final_kernel(const float* __restrict__ zz, float* __restrict__ out) {
    __shared__ float s[3 * 2048];
    __shared__ float Rs[144];
    const int bg = blockIdx.x;
    const long base = (long)bg * 3 * 2048;
    const int t = threadIdx.x;
    const float4* src = (const float4*)(zz + base);
    float4* dst = (float4*)s;
    for (int i = t; i < 1536; i += 288) dst[i] = src[i];
    __syncthreads();

    const int w = t >> 5, lane = t & 31;
    const int n = w / 3, m = w % 3;
    const float* za = s + n * 2048;
    const float* zb = s + m * 2048 + 1024;
#pragma unroll
    for (int r = 0; r < 16; r++) {
        float part = za[r * 64 + lane] * zb[r * 64 + lane]
                   + za[r * 64 + 32 + lane] * zb[r * 64 + 32 + lane];
#pragma unroll
        for (int o = 16; o; o >>= 1) part += __shfl_xor_sync(0xffffffffu, part, o);
        if (lane == 0) Rs[(n * 3 + m) * 16 + r] = part;
    }
    __syncthreads();

    if (t < 64) {
        const float* f = g_fsym + t * 144;
        float acc = 0.f;
#pragma unroll 16
        for (int i = 0; i < 144; i++) acc += Rs[i] * f[i];
        out[(long)bg * 64 + t] = acc;
    }
}

// ---------------- launch -----------------------------------------------------
extern "C" void kernel_launch(void* const* d_in, const int* in_sizes, int n_in,
                              void* d_out, int out_size) {
    (void)in_sizes; (void)n_in; (void)out_size;
    const float* x       = (const float*)d_in[0];   // (B,N,D)
    const float* filters = (const float*)d_in[1];   // (NF,3,3,16)
    const float* qe      = (const float*)d_in[2];   // (192,64)
    const float* wkmap   = (const float*)d_in[3];   // (256,64)
    const float* Wq      = (const float*)d_in[4];   // (16,256,64)
    const float* Wk      = (const float*)d_in[5];   // (16,256,64)
    float* out = (float*)d_out;                     // (B,G,NF) f32

    float *pk, *psc, *pg, *pzz, *pwt;
    cudaGetSymbolAddress((void**)&pk,  g_k);
    cudaGetSymbolAddress((void**)&psc, g_sc);
    cudaGetSymbolAddress((void**)&pg,  g_gobj);
    cudaGetSymbolAddress((void**)&pzz, g_zz);
    cudaGetSymbolAddress((void**)&pwt, g_wt);

    pe_kernel<<<(Nn * KDc + 255) / 256, 256>>>();
    fsym_kernel<<<(NFc * 144 + 255) / 256, 256>>>(filters);
    wtrans_kernel<<<(Dd * 2048 + 255) / 256, 256>>>(Wq, Wk);

    // k = x @ Wk_map + PE : (131072 x 64 x 256)
    {
        dim3 g(1, (Bsz * Nn) / 128, 1);
        gemm_tile<128, 64, 128, false, true><<<g, 128>>>(
            x, wkmap, pk, Bsz * Nn, KDc, Dd, 0, 0, 0, 1.0f);
    }
    // logits = beta * qe @ k[b]^T : batched (192 x 1024 x 64)
    {
        dim3 g(Nn / 128, Qq / 64, Bsz);
        gemm_tile<64, 128, 128, true, false><<<g, 128>>>(
            qe, pk, psc, Qq, Nn, KDc,
            0, (long)Nn * KDc, (long)Qq * Nn, 0.125f);
    }
    softmax_kernel<<<Bsz * Qq, 256>>>(psc);
    // gobj = scores @ x : batched (192 x 256 x 1024)
    {
        dim3 g(Dd / 128, Qq / 64, Bsz);
        gemm_tile<64, 128, 128, false, false><<<g, 128>>>(
            psc, x, pg, Qq, Dd, Nn,
            (long)Qq * Nn, (long)Nn * Dd, (long)Qq * Dd, 1.0f);
    }
    // zz = gobj @ W' : (24576 x 2048 x 256)  [zq | zk]
    {
        dim3 g(2048 / 128, (Bsz * Qq) / 128, 1);
        gemm_tile<128, 128, 256, false, false><<<g, 256>>>(
            pg, pwt, pzz, Bsz * Qq, 2048, Dd, 0, 0, 0, 1.0f);
    }
    final_kernel<<<Bsz * Gg, 288>>>(pzz, out);
}

// round 9
// speedup vs baseline: 2.9688x; 2.9688x over previous
#include <cuda_runtime.h>
#include <math.h>
#include <stdint.h>

// Problem dims
#define Bsz  128
#define Nn   1024
#define Dd   256
#define Gg   64
#define RELD 16
#define KDc  64
#define Qq   192
#define QP   256   // q padded to multiple of 128

// ---------------- scratch (static device globals; zero-init, no allocs) -----
__device__ float g_pe[Nn * KDc];
__device__ float g_fsym[64 * 144];
__device__ float g_wt2[2048 * 256];               // (c=r*64+p, d) K-major, rna
__device__ float g_wkT[64 * 256];                 // (kd, d) K-major, rna
__device__ float g_qer[Qq * KDc];                 // rna copy of query_emb
__device__ float g_xr[(long)Bsz * Nn * Dd];       // rna copy of x
__device__ float g_xT[(long)Bsz * Dd * Nn];       // x transposed (b,d,n), rna
__device__ float g_k[(long)Bsz * Nn * KDc];       // keys (rna'd in epilogue)
__device__ float g_scT[(long)Bsz * Nn * Qq];      // logits^T (b,n,q)
__device__ float g_S[(long)Bsz * QP * Nn];        // scores (b,qpad,n); rows>=192 stay 0
__device__ float g_gobj[(long)Bsz * Qq * Dd];     // (b*192+q, d), rna
__device__ float g_zz[(long)Bsz * Qq * 2048];     // zq|zk

// ---------------- helpers ----------------------------------------------------
__device__ __forceinline__ uint32_t smem_u32(const void* p) {
    uint32_t a;
    asm("{ .reg .u64 t; cvta.to.shared.u64 t, %1; cvt.u32.u64 %0, t; }"
        : "=r"(a) : "l"(p));
    return a;
}
__device__ __forceinline__ float rna_tf32(float x) {
    uint32_t u;
    asm("cvt.rna.tf32.f32 %0, %1;" : "=r"(u) : "f"(x));
    return __uint_as_float(u);
}
__device__ __forceinline__ void cpa16(uint32_t dst, const void* src) {
    asm volatile("cp.async.ca.shared.global [%0], [%1], 16;"
                 :: "r"(dst), "l"(src) : "memory");
}
__device__ __forceinline__ void mma8(float* c, const uint32_t* a, const uint32_t* b) {
    asm volatile(
        "mma.sync.aligned.m16n8k8.row.col.f32.tf32.tf32.f32 "
        "{%0,%1,%2,%3}, {%4,%5,%6,%7}, {%8,%9}, {%0,%1,%2,%3};"
        : "+f"(c[0]), "+f"(c[1]), "+f"(c[2]), "+f"(c[3])
        : "r"(a[0]), "r"(a[1]), "r"(a[2]), "r"(a[3]), "r"(b[0]), "r"(b[1]));
}

// ---------------- tf32 mma.sync NT GEMM --------------------------------------
// A: (M x K) K-major, B: (N x K) K-major, C = alpha * A @ B^T row-major.
// BK=32, warp tile 64x32, cp.async double buffer, XOR-swizzled smem.
// EPI: 0 plain, 1 +PE then rna (k-proj), 2 alpha (logits), 3 rna (gobj)
template<int BM, int BN, int EPI>
__global__ __launch_bounds__((BM / 64) * (BN / 32) * 32, 2)
void mma_gemm(const float* __restrict__ A, const float* __restrict__ B,
              float* __restrict__ C, int K, int N,
              long sA, long sB, long sC, float alpha, int rowclip) {
    constexpr int THREADS = (BM / 64) * (BN / 32) * 32;
    constexpr int WN = BN / 32;            // warps along N
    constexpr int STG = (BM + BN) * 32;    // floats per stage
    constexpr int CA = BM * 8 / THREADS;   // float4 chunks of A per thread
    constexpr int CB = BN * 8 / THREADS;
    extern __shared__ float sm[];
    const uint32_t smb = smem_u32(sm);

    const int t = threadIdx.x;
    const int wid = t >> 5, lane = t & 31;
    const int l4 = lane >> 2, lm4 = lane & 3;
    const int mBase = (wid / WN) * 64;
    const int nBase = (wid % WN) * 32;

    A += (long)blockIdx.z * sA + (long)(blockIdx.y * BM) * K;
    B += (long)blockIdx.z * sB + (long)(blockIdx.x * BN) * K;
    C += (long)blockIdx.z * sC;

    auto load_stage = [&](int kt, int sb) {
        const int k0 = kt * 32;
        uint32_t ab = smb + sb * (STG * 4);
#pragma unroll
        for (int i = 0; i < CA; i++) {
            int id = t + i * THREADS;
            int row = id >> 3, kb = id & 7;
            uint32_t dst = ab + (uint32_t)((row * 32 + ((kb ^ (row & 7)) << 2)) * 4);
            cpa16(dst, A + (long)row * K + k0 + kb * 4);
        }
        uint32_t bb = ab + BM * 32 * 4;
#pragma unroll
        for (int i = 0; i < CB; i++) {
            int id = t + i * THREADS;
            int row = id >> 3, kb = id & 7;
            uint32_t dst = bb + (uint32_t)((row * 32 + ((kb ^ (row & 7)) << 2)) * 4);
            cpa16(dst, B + (long)row * K + k0 + kb * 4);
        }
        asm volatile("cp.async.commit_group;" ::: "memory");
    };

    float acc[4][4][4] = {};
    const int KT = K / 32;
    load_stage(0, 0);

    for (int kt = 0; kt < KT; kt++) {
        if (kt + 1 < KT) {
            load_stage(kt + 1, (kt + 1) & 1);
            asm volatile("cp.async.wait_group 1;" ::: "memory");
        } else {
            asm volatile("cp.async.wait_group 0;" ::: "memory");
        }
        __syncthreads();
        const float* As = sm + (kt & 1) * STG;
        const float* Bs = As + BM * 32;
#pragma unroll
        for (int ks = 0; ks < 4; ks++) {
            const int cx0 = lm4 + ((((2 * ks) ^ l4) & 7) << 2);
            const int cx1 = lm4 + ((((2 * ks + 1) ^ l4) & 7) << 2);
            uint32_t a[4][4];
#pragma unroll
            for (int mt = 0; mt < 4; mt++) {
                int r = mBase + mt * 16 + l4;
                a[mt][0] = __float_as_uint(As[r * 32 + cx0]);
                a[mt][1] = __float_as_uint(As[(r + 8) * 32 + cx0]);
                a[mt][2] = __float_as_uint(As[r * 32 + cx1]);
                a[mt][3] = __float_as_uint(As[(r + 8) * 32 + cx1]);
            }
            uint32_t b[4][2];
#pragma unroll
            for (int nt = 0; nt < 4; nt++) {
                int n = nBase + nt * 8 + l4;
                b[nt][0] = __float_as_uint(Bs[n * 32 + cx0]);
                b[nt][1] = __float_as_uint(Bs[n * 32 + cx1]);
            }
#pragma unroll
            for (int mt = 0; mt < 4; mt++)
#pragma unroll
                for (int nt = 0; nt < 4; nt++)
                    mma8(acc[mt][nt], a[mt], b[nt]);
        }
        __syncthreads();
    }

    // epilogue
    const int gn0 = blockIdx.x * BN + nBase;
#pragma unroll
    for (int mt = 0; mt < 4; mt++) {
        int gr0 = blockIdx.y * BM + mBase + mt * 16 + l4;
#pragma unroll
        for (int h = 0; h < 2; h++) {
            int gr = gr0 + 8 * h;
            if (gr >= rowclip) continue;
            float* crow = C + (long)gr * N + gn0;
            const float* pe = (EPI == 1) ? &g_pe[(gr & (Nn - 1)) * KDc + gn0] : (const float*)0;
#pragma unroll
            for (int nt = 0; nt < 4; nt++) {
                int gc = nt * 8 + 2 * lm4;
                float2 v;
                v.x = acc[mt][nt][2 * h + 0] * alpha;
                v.y = acc[mt][nt][2 * h + 1] * alpha;
                if (EPI == 1) { v.x += pe[gc]; v.y += pe[gc + 1]; }
                if (EPI == 1 || EPI == 3) { v.x = rna_tf32(v.x); v.y = rna_tf32(v.y); }
                *(float2*)&crow[gc] = v;
            }
        }
    }
}

// ---------------- precompute kernels -----------------------------------------
__global__ void pe_kernel() {
    int idx = blockIdx.x * blockDim.x + threadIdx.x;
    if (idx >= Nn * KDc) return;
    int n = idx >> 6, j = idx & 63;
    float e = (float)(j & ~1) / 64.0f;
    float angle = (float)n / powf(10000.0f, e);
    double a = (double)angle;
    g_pe[idx] = (j & 1) ? (float)cos(a) : (float)sin(a);
}

__global__ void fsym_kernel(const float* __restrict__ filters) {
    int idx = blockIdx.x * blockDim.x + threadIdx.x;
    if (idx >= 64 * 144) return;
    int f = idx / 144, rem = idx % 144;
    int n = rem / 48, m = (rem / 16) % 3, r = rem & 15;
    const int P[6][3] = {{0,1,2},{0,2,1},{1,0,2},{1,2,0},{2,0,1},{2,1,0}};
    float s = 0.f;
#pragma unroll
    for (int p = 0; p < 6; p++)
        s += filters[f * 144 + P[p][n] * 48 + P[p][m] * 16 + r];
    g_fsym[idx] = s * (1.0f / 6.0f);
}

__global__ void wt2_kernel(const float* __restrict__ Wq, const float* __restrict__ Wk) {
    int idx = blockIdx.x * blockDim.x + threadIdx.x;
    if (idx >= 2048 * 256) return;
    int c = idx >> 8, d = idx & 255;
    const float* W = (c < 1024) ? Wq : Wk;
    int cc = c & 1023, r = cc >> 6, p = cc & 63;
    g_wt2[idx] = rna_tf32(W[(r << 14) + (d << 6) + p]);
}

__global__ void smallprep_kernel(const float* __restrict__ wkmap, const float* __restrict__ qe) {
    int idx = blockIdx.x * blockDim.x + threadIdx.x;
    if (idx < 64 * 256) {
        int kd = idx >> 8, d = idx & 255;
        g_wkT[idx] = rna_tf32(wkmap[d * 64 + kd]);
    }
    if (idx < Qq * KDc) g_qer[idx] = rna_tf32(qe[idx]);
}

// x (b,n,d) -> xr (rna copy) + xT (b,d,n) rna
__global__ void xprep_kernel(const float* __restrict__ x) {
    __shared__ float tl[32][33];
    int b = blockIdx.z, n0 = blockIdx.x * 32, d0 = blockIdx.y * 32;
    int tx = threadIdx.x, ty = threadIdx.y;
    const float* xb = x + (long)b * Nn * Dd;
    float* xrb = g_xr + (long)b * Nn * Dd;
    float* xtb = g_xT + (long)b * Dd * Nn;
#pragma unroll
    for (int j = 0; j < 32; j += 8) {
        float v = rna_tf32(xb[(long)(n0 + ty + j) * Dd + d0 + tx]);
        xrb[(long)(n0 + ty + j) * Dd + d0 + tx] = v;
        tl[ty + j][tx] = v;
    }
    __syncthreads();
#pragma unroll
    for (int j = 0; j < 32; j += 8)
        xtb[(long)(d0 + ty + j) * Nn + n0 + tx] = tl[tx][ty + j];
}

// scT (b,1024,192) -> S (b,QP,1024); rows q>=192 stay zero (never written)
__global__ void trS_kernel() {
    __shared__ float tl[32][33];
    int b = blockIdx.z, n0 = blockIdx.x * 32, q0 = blockIdx.y * 32;
    int tx = threadIdx.x, ty = threadIdx.y;
    const float* in = g_scT + (long)b * Nn * Qq;
    float* out = g_S + (long)b * QP * Nn;
#pragma unroll
    for (int j = 0; j < 32; j += 8)
        tl[ty + j][tx] = in[(long)(n0 + ty + j) * Qq + q0 + tx];
    __syncthreads();
#pragma unroll
    for (int j = 0; j < 32; j += 8)
        out[(long)(q0 + ty + j) * Nn + n0 + tx] = tl[tx][ty + j];
}

// row softmax over 1024 on S rows (b,q<192), output rna-rounded
__global__ __launch_bounds__(256)
void softmax_kernel() {
    __shared__ float red_m[8], red_s[8];
    int bq = blockIdx.x;
    int b = bq / Qq, q = bq % Qq;
    float* p = g_S + ((long)b * QP + q) * 1024;
    int t = threadIdx.x;
    float4 v = ((float4*)p)[t];
    float m = fmaxf(fmaxf(v.x, v.y), fmaxf(v.z, v.w));
#pragma unroll
    for (int o = 16; o; o >>= 1) m = fmaxf(m, __shfl_xor_sync(0xffffffffu, m, o));
    if ((t & 31) == 0) red_m[t >> 5] = m;
    __syncthreads();
    float bm = red_m[0];
#pragma unroll
    for (int i = 1; i < 8; i++) bm = fmaxf(bm, red_m[i]);
    v.x = expf(v.x - bm); v.y = expf(v.y - bm);
    v.z = expf(v.z - bm); v.w = expf(v.w - bm);
    float s = v.x + v.y + v.z + v.w;
#pragma unroll
    for (int o = 16; o; o >>= 1) s += __shfl_xor_sync(0xffffffffu, s, o);
    if ((t & 31) == 0) red_s[t >> 5] = s;
    __syncthreads();
    float tot = red_s[0];
#pragma unroll
    for (int i = 1; i < 8; i++) tot += red_s[i];
    float inv = 1.0f / tot;
    v.x = rna_tf32(v.x * inv); v.y = rna_tf32(v.y * inv);
    v.z = rna_tf32(v.z * inv); v.w = rna_tf32(v.w * inv);
    ((float4*)p)[t] = v;
}

// ---------------- final: R[n,m,r] then contract with Fsym --------------------
__global__ __launch_bounds__(288)
void final_kernel(const float* __restrict__ zz, float* __restrict__ out) {
    __shared__ float s[3 * 2048];
    __shared__ float Rs[144];
    const int bg = blockIdx.x;
    const long base = (long)bg * 3 * 2048;
    const int t = threadIdx.x;
    const float4* src = (const float4*)(zz + base);
    float4* dst = (float4*)s;
    for (int i = t; i < 1536; i += 288) dst[i] = src[i];
    __syncthreads();

    const int w = t >> 5, lane = t & 31;
    const int n = w / 3, m = w % 3;
    const float* za = s + n * 2048;
    const float* zb = s + m * 2048 + 1024;
#pragma unroll
    for (int r = 0; r < 16; r++) {
        float part = za[r * 64 + lane] * zb[r * 64 + lane]
                   + za[r * 64 + 32 + lane] * zb[r * 64 + 32 + lane];
#pragma unroll
        for (int o = 16; o; o >>= 1) part += __shfl_xor_sync(0xffffffffu, part, o);
        if (lane == 0) Rs[(n * 3 + m) * 16 + r] = part;
    }
    __syncthreads();

    if (t < 64) {
        const float* f = g_fsym + t * 144;
        float acc = 0.f;
#pragma unroll 16
        for (int i = 0; i < 144; i++) acc += Rs[i] * f[i];
        out[(long)bg * 64 + t] = acc;
    }
}

// ---------------- launch -----------------------------------------------------
extern "C" void kernel_launch(void* const* d_in, const int* in_sizes, int n_in,
                              void* d_out, int out_size) {
    (void)in_sizes; (void)n_in; (void)out_size;
    const float* x       = (const float*)d_in[0];
    const float* filters = (const float*)d_in[1];
    const float* qe      = (const float*)d_in[2];
    const float* wkmap   = (const float*)d_in[3];
    const float* Wq      = (const float*)d_in[4];
    const float* Wk      = (const float*)d_in[5];
    float* out = (float*)d_out;

    float *pxr, *pxT, *pk, *pscT, *pS, *pg, *pzz, *pwt2, *pwkT, *pqer;
    cudaGetSymbolAddress((void**)&pxr,  g_xr);
    cudaGetSymbolAddress((void**)&pxT,  g_xT);
    cudaGetSymbolAddress((void**)&pk,   g_k);
    cudaGetSymbolAddress((void**)&pscT, g_scT);
    cudaGetSymbolAddress((void**)&pS,   g_S);
    cudaGetSymbolAddress((void**)&pg,   g_gobj);
    cudaGetSymbolAddress((void**)&pzz,  g_zz);
    cudaGetSymbolAddress((void**)&pwt2, g_wt2);
    cudaGetSymbolAddress((void**)&pwkT, g_wkT);
    cudaGetSymbolAddress((void**)&pqer, g_qer);

    const int SM_A = 2 * (128 + 64)  * 32 * 4;   // 49152
    const int SM_B = 2 * (128 + 128) * 32 * 4;   // 65536
    cudaFuncSetAttribute(mma_gemm<128, 64, 1>,  cudaFuncAttributeMaxDynamicSharedMemorySize, SM_A);
    cudaFuncSetAttribute(mma_gemm<128, 64, 2>,  cudaFuncAttributeMaxDynamicSharedMemorySize, SM_A);
    cudaFuncSetAttribute(mma_gemm<128, 128, 3>, cudaFuncAttributeMaxDynamicSharedMemorySize, SM_B);
    cudaFuncSetAttribute(mma_gemm<128, 128, 0>, cudaFuncAttributeMaxDynamicSharedMemorySize, SM_B);

    pe_kernel<<<(Nn * KDc + 255) / 256, 256>>>();
    fsym_kernel<<<(64 * 144 + 255) / 256, 256>>>(filters);
    wt2_kernel<<<(2048 * 256 + 255) / 256, 256>>>(Wq, Wk);
    smallprep_kernel<<<(64 * 256 + 255) / 256, 256>>>(wkmap, qe);
    xprep_kernel<<<dim3(32, 8, Bsz), dim3(32, 8)>>>(x);

    // k = rna(xr @ wkT^T + PE) : M=131072, N=64, K=256
    mma_gemm<128, 64, 1><<<dim3(1, 1024, 1), 128, SM_A>>>(
        pxr, pwkT, pk, 256, 64, 0, 0, 0, 1.0f, 1 << 30);

    // scT[b] = 0.125 * k[b] @ qe^T : per b M=1024, N=192, K=64
    mma_gemm<128, 64, 2><<<dim3(3, 8, Bsz), 128, SM_A>>>(
        pk, pqer, pscT, 64, 192,
        (long)Nn * KDc, 0, (long)Nn * Qq, 0.125f, 1 << 30);

    trS_kernel<<<dim3(32, 6, Bsz), dim3(32, 8)>>>();
    softmax_kernel<<<Bsz * Qq, 256>>>();

    // gobj[b] = rna(S[b] @ xT[b]^T), clip q<192 : M=256(pad), N=256, K=1024
    mma_gemm<128, 128, 3><<<dim3(2, 2, Bsz), 256, SM_B>>>(
        pS, pxT, pg, 1024, 256,
        (long)QP * Nn, (long)Dd * Nn, (long)Qq * Dd, 1.0f, Qq);

    // zz = gobj @ wt2^T : M=24576, N=2048, K=256
    mma_gemm<128, 128, 0><<<dim3(16, 192, 1), 256, SM_B>>>(
        pg, pwt2, pzz, 256, 2048, 0, 0, 0, 1.0f, 1 << 30);

    final_kernel<<<Bsz * Gg, 288>>>(pzz, out);
}

// round 10
// speedup vs baseline: 3.2780x; 1.1041x over previous
#include <cuda_runtime.h>
#include <math.h>
#include <stdint.h>

// Problem dims
#define Bsz  128
#define Nn   1024
#define Dd   256
#define Gg   64
#define RELD 16
#define KDc  64
#define Qq   192
#define QP   256   // row stride of score buffer (padding unused now)

// ---------------- scratch (static device globals; zero-init, no allocs) -----
__device__ float g_pe[Nn * KDc];
__device__ float g_fsym[64 * 144];
__device__ float g_wt2[2048 * 256];               // (c=r*64+p, d) K-major, rna
__device__ float g_wkT[64 * 256];                 // (kd, d) K-major, rna
__device__ float g_qer[Qq * KDc];                 // rna copy of query_emb
__device__ float g_xT[(long)Bsz * Dd * Nn];       // x transposed (b,d,n), rna
__device__ float g_k[(long)Bsz * Nn * KDc];       // keys (rna'd in epilogue)
__device__ float g_S[(long)Bsz * QP * Nn];        // scores (b,q,n), q<192 used
__device__ float g_gobj[(long)Bsz * Qq * Dd];     // (b*192+q, d), rna
__device__ float g_zz[(long)Bsz * Qq * 2048];     // zq|zk

// ---------------- helpers ----------------------------------------------------
__device__ __forceinline__ uint32_t smem_u32(const void* p) {
    uint32_t a;
    asm("{ .reg .u64 t; cvta.to.shared.u64 t, %1; cvt.u32.u64 %0, t; }"
        : "=r"(a) : "l"(p));
    return a;
}
__device__ __forceinline__ float rna_tf32(float x) {
    uint32_t u;
    asm("cvt.rna.tf32.f32 %0, %1;" : "=r"(u) : "f"(x));
    return __uint_as_float(u);
}
__device__ __forceinline__ uint32_t rna_bits(float x) {
    uint32_t u;
    asm("cvt.rna.tf32.f32 %0, %1;" : "=r"(u) : "f"(x));
    return u;
}
__device__ __forceinline__ void cpa16(uint32_t dst, const void* src) {
    asm volatile("cp.async.ca.shared.global [%0], [%1], 16;"
                 :: "r"(dst), "l"(src) : "memory");
}
__device__ __forceinline__ void mma8(float* c, const uint32_t* a, const uint32_t* b) {
    asm volatile(
        "mma.sync.aligned.m16n8k8.row.col.f32.tf32.tf32.f32 "
        "{%0,%1,%2,%3}, {%4,%5,%6,%7}, {%8,%9}, {%0,%1,%2,%3};"
        : "+f"(c[0]), "+f"(c[1]), "+f"(c[2]), "+f"(c[3])
        : "r"(a[0]), "r"(a[1]), "r"(a[2]), "r"(a[3]), "r"(b[0]), "r"(b[1]));
}

// ---------------- tf32 mma.sync NT GEMM --------------------------------------
// A: (M x K) K-major, B: (N x K) K-major, C = alpha * A @ B^T row-major.
// BK=32, warp tile 64x32, cp.async double buffer, XOR-swizzled smem.
// EPI: 0 plain, 1 +PE then rna (k-proj), 2 alpha (logits), 3 rna (gobj)
// RNAA: apply cvt.rna.tf32 to A fragments (A read from un-rounded gmem)
template<int BM, int BN, int EPI, bool RNAA>
__global__ __launch_bounds__((BM / 64) * (BN / 32) * 32, 2)
void mma_gemm(const float* __restrict__ A, const float* __restrict__ B,
              float* __restrict__ C, int K, int N,
              long sA, long sB, long sC, float alpha) {
    constexpr int THREADS = (BM / 64) * (BN / 32) * 32;
    constexpr int WN = BN / 32;            // warps along N
    constexpr int STG = (BM + BN) * 32;    // floats per stage
    constexpr int CA = BM * 8 / THREADS;   // float4 chunks of A per thread
    constexpr int CB = BN * 8 / THREADS;
    extern __shared__ float sm[];
    const uint32_t smb = smem_u32(sm);

    const int t = threadIdx.x;
    const int wid = t >> 5, lane = t & 31;
    const int l4 = lane >> 2, lm4 = lane & 3;
    const int mBase = (wid / WN) * 64;
    const int nBase = (wid % WN) * 32;

    A += (long)blockIdx.z * sA + (long)(blockIdx.y * BM) * K;
    B += (long)blockIdx.z * sB + (long)(blockIdx.x * BN) * K;
    C += (long)blockIdx.z * sC;

    auto load_stage = [&](int kt, int sb) {
        const int k0 = kt * 32;
        uint32_t ab = smb + sb * (STG * 4);
#pragma unroll
        for (int i = 0; i < CA; i++) {
            int id = t + i * THREADS;
            int row = id >> 3, kb = id & 7;
            uint32_t dst = ab + (uint32_t)((row * 32 + ((kb ^ (row & 7)) << 2)) * 4);
            cpa16(dst, A + (long)row * K + k0 + kb * 4);
        }
        uint32_t bb = ab + BM * 32 * 4;
#pragma unroll
        for (int i = 0; i < CB; i++) {
            int id = t + i * THREADS;
            int row = id >> 3, kb = id & 7;
            uint32_t dst = bb + (uint32_t)((row * 32 + ((kb ^ (row & 7)) << 2)) * 4);
            cpa16(dst, B + (long)row * K + k0 + kb * 4);
        }
        asm volatile("cp.async.commit_group;" ::: "memory");
    };

    float acc[4][4][4] = {};
    const int KT = K / 32;
    load_stage(0, 0);

    for (int kt = 0; kt < KT; kt++) {
        if (kt + 1 < KT) {
            load_stage(kt + 1, (kt + 1) & 1);
            asm volatile("cp.async.wait_group 1;" ::: "memory");
        } else {
            asm volatile("cp.async.wait_group 0;" ::: "memory");
        }
        __syncthreads();
        const float* As = sm + (kt & 1) * STG;
        const float* Bs = As + BM * 32;
#pragma unroll
        for (int ks = 0; ks < 4; ks++) {
            const int cx0 = lm4 + ((((2 * ks) ^ l4) & 7) << 2);
            const int cx1 = lm4 + ((((2 * ks + 1) ^ l4) & 7) << 2);
            uint32_t a[4][4];
#pragma unroll
            for (int mt = 0; mt < 4; mt++) {
                int r = mBase + mt * 16 + l4;
                if (RNAA) {
                    a[mt][0] = rna_bits(As[r * 32 + cx0]);
                    a[mt][1] = rna_bits(As[(r + 8) * 32 + cx0]);
                    a[mt][2] = rna_bits(As[r * 32 + cx1]);
                    a[mt][3] = rna_bits(As[(r + 8) * 32 + cx1]);
                } else {
                    a[mt][0] = __float_as_uint(As[r * 32 + cx0]);
                    a[mt][1] = __float_as_uint(As[(r + 8) * 32 + cx0]);
                    a[mt][2] = __float_as_uint(As[r * 32 + cx1]);
                    a[mt][3] = __float_as_uint(As[(r + 8) * 32 + cx1]);
                }
            }
            uint32_t b[4][2];
#pragma unroll
            for (int nt = 0; nt < 4; nt++) {
                int n = nBase + nt * 8 + l4;
                b[nt][0] = __float_as_uint(Bs[n * 32 + cx0]);
                b[nt][1] = __float_as_uint(Bs[n * 32 + cx1]);
            }
#pragma unroll
            for (int mt = 0; mt < 4; mt++)
#pragma unroll
                for (int nt = 0; nt < 4; nt++)
                    mma8(acc[mt][nt], a[mt], b[nt]);
        }
        __syncthreads();
    }

    // epilogue
    const int gn0 = blockIdx.x * BN + nBase;
#pragma unroll
    for (int mt = 0; mt < 4; mt++) {
        int gr0 = blockIdx.y * BM + mBase + mt * 16 + l4;
#pragma unroll
        for (int h = 0; h < 2; h++) {
            int gr = gr0 + 8 * h;
            float* crow = C + (long)gr * N + gn0;
            const float* pe = (EPI == 1) ? &g_pe[(gr & (Nn - 1)) * KDc + gn0] : (const float*)0;
#pragma unroll
            for (int nt = 0; nt < 4; nt++) {
                int gc = nt * 8 + 2 * lm4;
                float2 v;
                v.x = acc[mt][nt][2 * h + 0] * alpha;
                v.y = acc[mt][nt][2 * h + 1] * alpha;
                if (EPI == 1) { v.x += pe[gc]; v.y += pe[gc + 1]; }
                if (EPI == 1 || EPI == 3) { v.x = rna_tf32(v.x); v.y = rna_tf32(v.y); }
                *(float2*)&crow[gc] = v;
            }
        }
    }
}

// ---------------- precompute kernels -----------------------------------------
__global__ void pe_kernel() {
    int idx = blockIdx.x * blockDim.x + threadIdx.x;
    if (idx >= Nn * KDc) return;
    int n = idx >> 6, j = idx & 63;
    float e = (float)(j & ~1) / 64.0f;
    float angle = (float)n / powf(10000.0f, e);
    double a = (double)angle;
    g_pe[idx] = (j & 1) ? (float)cos(a) : (float)sin(a);
}

__global__ void fsym_kernel(const float* __restrict__ filters) {
    int idx = blockIdx.x * blockDim.x + threadIdx.x;
    if (idx >= 64 * 144) return;
    int f = idx / 144, rem = idx % 144;
    int n = rem / 48, m = (rem / 16) % 3, r = rem & 15;
    const int P[6][3] = {{0,1,2},{0,2,1},{1,0,2},{1,2,0},{2,0,1},{2,1,0}};
    float s = 0.f;
#pragma unroll
    for (int p = 0; p < 6; p++)
        s += filters[f * 144 + P[p][n] * 48 + P[p][m] * 16 + r];
    g_fsym[idx] = s * (1.0f / 6.0f);
}

__global__ void wt2_kernel(const float* __restrict__ Wq, const float* __restrict__ Wk) {
    int idx = blockIdx.x * blockDim.x + threadIdx.x;
    if (idx >= 2048 * 256) return;
    int c = idx >> 8, d = idx & 255;
    const float* W = (c < 1024) ? Wq : Wk;
    int cc = c & 1023, r = cc >> 6, p = cc & 63;
    g_wt2[idx] = rna_tf32(W[(r << 14) + (d << 6) + p]);
}

__global__ void smallprep_kernel(const float* __restrict__ wkmap, const float* __restrict__ qe) {
    int idx = blockIdx.x * blockDim.x + threadIdx.x;
    if (idx < 64 * 256) {
        int kd = idx >> 8, d = idx & 255;
        g_wkT[idx] = rna_tf32(wkmap[d * 64 + kd]);
    }
    if (idx < Qq * KDc) g_qer[idx] = rna_tf32(qe[idx]);
}

// x (b,n,d) -> xT (b,d,n) rna
__global__ void xprep_kernel(const float* __restrict__ x) {
    __shared__ float tl[32][33];
    int b = blockIdx.z, n0 = blockIdx.x * 32, d0 = blockIdx.y * 32;
    int tx = threadIdx.x, ty = threadIdx.y;
    const float* xb = x + (long)b * Nn * Dd;
    float* xtb = g_xT + (long)b * Dd * Nn;
#pragma unroll
    for (int j = 0; j < 32; j += 8)
        tl[ty + j][tx] = rna_tf32(xb[(long)(n0 + ty + j) * Dd + d0 + tx]);
    __syncthreads();
#pragma unroll
    for (int j = 0; j < 32; j += 8)
        xtb[(long)(d0 + ty + j) * Nn + n0 + tx] = tl[tx][ty + j];
}

// row softmax over 1024 on S rows (b,q<192), output rna-rounded
__global__ __launch_bounds__(256)
void softmax_kernel() {
    __shared__ float red_m[8], red_s[8];
    int bq = blockIdx.x;
    int b = bq / Qq, q = bq % Qq;
    float* p = g_S + ((long)b * QP + q) * 1024;
    int t = threadIdx.x;
    float4 v = ((float4*)p)[t];
    float m = fmaxf(fmaxf(v.x, v.y), fmaxf(v.z, v.w));
#pragma unroll
    for (int o = 16; o; o >>= 1) m = fmaxf(m, __shfl_xor_sync(0xffffffffu, m, o));
    if ((t & 31) == 0) red_m[t >> 5] = m;
    __syncthreads();
    float bm = red_m[0];
#pragma unroll
    for (int i = 1; i < 8; i++) bm = fmaxf(bm, red_m[i]);
    v.x = expf(v.x - bm); v.y = expf(v.y - bm);
    v.z = expf(v.z - bm); v.w = expf(v.w - bm);
    float s = v.x + v.y + v.z + v.w;
#pragma unroll
    for (int o = 16; o; o >>= 1) s += __shfl_xor_sync(0xffffffffu, s, o);
    if ((t & 31) == 0) red_s[t >> 5] = s;
    __syncthreads();
    float tot = red_s[0];
#pragma unroll
    for (int i = 1; i < 8; i++) tot += red_s[i];
    float inv = 1.0f / tot;
    v.x = rna_tf32(v.x * inv); v.y = rna_tf32(v.y * inv);
    v.z = rna_tf32(v.z * inv); v.w = rna_tf32(v.w * inv);
    ((float4*)p)[t] = v;
}

// ---------------- final: R[n,m,r] then contract with Fsym --------------------
__global__ __launch_bounds__(288)
void final_kernel(const float* __restrict__ zz, float* __restrict__ out) {
    __shared__ float s[3 * 2048];
    __shared__ float Rs[144];
    const int bg = blockIdx.x;
    const long base = (long)bg * 3 * 2048;
    const int t = threadIdx.x;
    const float4* src = (const float4*)(zz + base);
    float4* dst = (float4*)s;
    for (int i = t; i < 1536; i += 288) dst[i] = src[i];
    __syncthreads();

    const int w = t >> 5, lane = t & 31;
    const int n = w / 3, m = w % 3;
    const float* za = s + n * 2048;
    const float* zb = s + m * 2048 + 1024;
#pragma unroll
    for (int r = 0; r < 16; r++) {
        float part = za[r * 64 + lane] * zb[r * 64 + lane]
                   + za[r * 64 + 32 + lane] * zb[r * 64 + 32 + lane];
#pragma unroll
        for (int o = 16; o; o >>= 1) part += __shfl_xor_sync(0xffffffffu, part, o);
        if (lane == 0) Rs[(n * 3 + m) * 16 + r] = part;
    }
    __syncthreads();

    if (t < 64) {
        const float* f = g_fsym + t * 144;
        float acc = 0.f;
#pragma unroll 16
        for (int i = 0; i < 144; i++) acc += Rs[i] * f[i];
        out[(long)bg * 64 + t] = acc;
    }
}

// ---------------- launch -----------------------------------------------------
extern "C" void kernel_launch(void* const* d_in, const int* in_sizes, int n_in,
                              void* d_out, int out_size) {
    (void)in_sizes; (void)n_in; (void)out_size;
    const float* x       = (const float*)d_in[0];
    const float* filters = (const float*)d_in[1];
    const float* qe      = (const float*)d_in[2];
    const float* wkmap   = (const float*)d_in[3];
    const float* Wq      = (const float*)d_in[4];
    const float* Wk      = (const float*)d_in[5];
    float* out = (float*)d_out;

    float *pxT, *pk, *pS, *pg, *pzz, *pwt2, *pwkT, *pqer;
    cudaGetSymbolAddress((void**)&pxT,  g_xT);
    cudaGetSymbolAddress((void**)&pk,   g_k);
    cudaGetSymbolAddress((void**)&pS,   g_S);
    cudaGetSymbolAddress((void**)&pg,   g_gobj);
    cudaGetSymbolAddress((void**)&pzz,  g_zz);
    cudaGetSymbolAddress((void**)&pwt2, g_wt2);
    cudaGetSymbolAddress((void**)&pwkT, g_wkT);
    cudaGetSymbolAddress((void**)&pqer, g_qer);

    const int SM_KP = 2 * (128 + 64)  * 32 * 4;   // 49152  (BM128,BN64)
    const int SM_SM = 2 * (64 + 128)  * 32 * 4;   // 49152  (BM64,BN128)
    const int SM_ZZ = 2 * (128 + 128) * 32 * 4;   // 65536  (BM128,BN128)
    cudaFuncSetAttribute((const void*)mma_gemm<128, 64, 1, true>,
                         cudaFuncAttributeMaxDynamicSharedMemorySize, SM_KP);
    cudaFuncSetAttribute((const void*)mma_gemm<64, 128, 2, false>,
                         cudaFuncAttributeMaxDynamicSharedMemorySize, SM_SM);
    cudaFuncSetAttribute((const void*)mma_gemm<64, 128, 3, false>,
                         cudaFuncAttributeMaxDynamicSharedMemorySize, SM_SM);
    cudaFuncSetAttribute((const void*)mma_gemm<128, 128, 0, false>,
                         cudaFuncAttributeMaxDynamicSharedMemorySize, SM_ZZ);

    pe_kernel<<<(Nn * KDc + 255) / 256, 256>>>();
    fsym_kernel<<<(64 * 144 + 255) / 256, 256>>>(filters);
    wt2_kernel<<<(2048 * 256 + 255) / 256, 256>>>(Wq, Wk);
    smallprep_kernel<<<(64 * 256 + 255) / 256, 256>>>(wkmap, qe);
    xprep_kernel<<<dim3(32, 8, Bsz), dim3(32, 8)>>>(x);

    // k = rna(x @ wkT^T + PE) : M=131072, N=64, K=256 ; A fragments rna'd
    mma_gemm<128, 64, 1, true><<<dim3(1, 1024, 1), 128, SM_KP>>>(
        x, pwkT, pk, 256, 64, 0, 0, 0, 1.0f);

    // S[b] = 0.125 * qe @ k[b]^T : per b M=192 (BM=64), N=1024, K=64
    mma_gemm<64, 128, 2, false><<<dim3(8, 3, Bsz), 128, SM_SM>>>(
        pqer, pk, pS, 64, 1024,
        0, (long)Nn * KDc, (long)QP * Nn, 0.125f);

    softmax_kernel<<<Bsz * Qq, 256>>>();

    // gobj[b] = rna(S[b] @ xT[b]^T) : M=192 (BM=64), N=256, K=1024
    mma_gemm<64, 128, 3, false><<<dim3(2, 3, Bsz), 128, SM_SM>>>(
        pS, pxT, pg, 1024, 256,
        (long)QP * Nn, (long)Dd * Nn, (long)Qq * Dd, 1.0f);

    // zz = gobj @ wt2^T : M=24576, N=2048, K=256
    mma_gemm<128, 128, 0, false><<<dim3(16, 192, 1), 256, SM_ZZ>>>(
        pg, pwt2, pzz, 256, 2048, 0, 0, 0, 1.0f);

    final_kernel<<<Bsz * Gg, 288>>>(pzz, out);
}

// round 12
// speedup vs baseline: 3.6565x; 1.1155x over previous
#include <cuda_runtime.h>
#include <math.h>
#include <stdint.h>

// Problem dims
#define Bsz  128
#define Nn   1024
#define Dd   256
#define Gg   64
#define RELD 16
#define KDc  64
#define Qq   192
#define QP   256   // row stride of score buffer

#define NBG  (Bsz * Gg)   // 8192

// ---------------- scratch (static device globals; zero-init, no allocs) -----
__device__ float g_pe[Nn * KDc];
__device__ float g_fsym[64 * 144];
__device__ float g_wt2[2048 * 256];               // (c=r*64+p, d) K-major, rna
__device__ float g_wkT[64 * 256];                 // (kd, d) K-major, rna
__device__ float g_qer[Qq * KDc];                 // rna copy of query_emb
__device__ float g_xT[(long)Bsz * Dd * Nn];       // x transposed (b,d,n), rna
__device__ float g_k[(long)Bsz * Nn * KDc];       // keys (rna'd in epilogue)
__device__ float g_S[(long)Bsz * QP * Nn];        // scores (b,q,n), q<192 used
__device__ float g_gobj[(long)Bsz * Qq * Dd];     // (b*192+q, d), rna
__device__ float g_R[(long)RELD * NBG * 9];       // R[r][bg][n*3+m]  (4.7MB)

// ---------------- helpers ----------------------------------------------------
__device__ __forceinline__ uint32_t smem_u32(const void* p) {
    uint32_t a;
    asm("{ .reg .u64 t; cvta.to.shared.u64 t, %1; cvt.u32.u64 %0, t; }"
        : "=r"(a) : "l"(p));
    return a;
}
__device__ __forceinline__ float rna_tf32(float x) {
    uint32_t u;
    asm("cvt.rna.tf32.f32 %0, %1;" : "=r"(u) : "f"(x));
    return __uint_as_float(u);
}
__device__ __forceinline__ uint32_t rna_bits(float x) {
    uint32_t u;
    asm("cvt.rna.tf32.f32 %0, %1;" : "=r"(u) : "f"(x));
    return u;
}
__device__ __forceinline__ void cpa16(uint32_t dst, const void* src) {
    asm volatile("cp.async.ca.shared.global [%0], [%1], 16;"
                 :: "r"(dst), "l"(src) : "memory");
}
__device__ __forceinline__ void mma8(float* c, const uint32_t* a, const uint32_t* b) {
    asm volatile(
        "mma.sync.aligned.m16n8k8.row.col.f32.tf32.tf32.f32 "
        "{%0,%1,%2,%3}, {%4,%5,%6,%7}, {%8,%9}, {%0,%1,%2,%3};"
        : "+f"(c[0]), "+f"(c[1]), "+f"(c[2]), "+f"(c[3])
        : "r"(a[0]), "r"(a[1]), "r"(a[2]), "r"(a[3]), "r"(b[0]), "r"(b[1]));
}

// ---------------- tf32 mma.sync NT GEMM --------------------------------------
// A: (M x K) K-major, B: (N x K) K-major, C = alpha * A @ B^T row-major.
// BK=32, warp tile 64x32, cp.async double buffer, XOR-swizzled smem.
// EPI: 0 plain, 1 +PE then rna (k-proj), 2 alpha (logits), 3 rna (gobj)
// RNAA: apply cvt.rna.tf32 to A fragments (A read from un-rounded gmem)
// WRXT: also emit rna'd transpose of the A tile to g_xT (k-proj only; BM=128)
template<int BM, int BN, int EPI, bool RNAA, bool WRXT>
__global__ __launch_bounds__((BM / 64) * (BN / 32) * 32, 2)
void mma_gemm(const float* __restrict__ A, const float* __restrict__ B,
              float* __restrict__ C, int K, int N,
              long sA, long sB, long sC, float alpha) {
    constexpr int THREADS = (BM / 64) * (BN / 32) * 32;
    constexpr int WN = BN / 32;            // warps along N
    constexpr int STG = (BM + BN) * 32;    // floats per stage
    constexpr int CA = BM * 8 / THREADS;   // float4 chunks of A per thread
    constexpr int CB = BN * 8 / THREADS;
    extern __shared__ float sm[];
    const uint32_t smb = smem_u32(sm);

    const int t = threadIdx.x;
    const int wid = t >> 5, lane = t & 31;
    const int l4 = lane >> 2, lm4 = lane & 3;
    const int mBase = (wid / WN) * 64;
    const int nBase = (wid % WN) * 32;

    A += (long)blockIdx.z * sA + (long)(blockIdx.y * BM) * K;
    B += (long)blockIdx.z * sB + (long)(blockIdx.x * BN) * K;
    C += (long)blockIdx.z * sC;

    auto load_stage = [&](int kt, int sb) {
        const int k0 = kt * 32;
        uint32_t ab = smb + sb * (STG * 4);
#pragma unroll
        for (int i = 0; i < CA; i++) {
            int id = t + i * THREADS;
            int row = id >> 3, kb = id & 7;
            uint32_t dst = ab + (uint32_t)((row * 32 + ((kb ^ (row & 7)) << 2)) * 4);
            cpa16(dst, A + (long)row * K + k0 + kb * 4);
        }
        uint32_t bb = ab + BM * 32 * 4;
#pragma unroll
        for (int i = 0; i < CB; i++) {
            int id = t + i * THREADS;
            int row = id >> 3, kb = id & 7;
            uint32_t dst = bb + (uint32_t)((row * 32 + ((kb ^ (row & 7)) << 2)) * 4);
            cpa16(dst, B + (long)row * K + k0 + kb * 4);
        }
        asm volatile("cp.async.commit_group;" ::: "memory");
    };

    float acc[4][4][4] = {};
    const int KT = K / 32;
    load_stage(0, 0);

    for (int kt = 0; kt < KT; kt++) {
        if (kt + 1 < KT) {
            load_stage(kt + 1, (kt + 1) & 1);
            asm volatile("cp.async.wait_group 1;" ::: "memory");
        } else {
            asm volatile("cp.async.wait_group 0;" ::: "memory");
        }
        __syncthreads();
        const float* As = sm + (kt & 1) * STG;
        const float* Bs = As + BM * 32;
#pragma unroll
        for (int ks = 0; ks < 4; ks++) {
            const int cx0 = lm4 + ((((2 * ks) ^ l4) & 7) << 2);
            const int cx1 = lm4 + ((((2 * ks + 1) ^ l4) & 7) << 2);
            uint32_t a[4][4];
#pragma unroll
            for (int mt = 0; mt < 4; mt++) {
                int r = mBase + mt * 16 + l4;
                if (RNAA) {
                    a[mt][0] = rna_bits(As[r * 32 + cx0]);
                    a[mt][1] = rna_bits(As[(r + 8) * 32 + cx0]);
                    a[mt][2] = rna_bits(As[r * 32 + cx1]);
                    a[mt][3] = rna_bits(As[(r + 8) * 32 + cx1]);
                } else {
                    a[mt][0] = __float_as_uint(As[r * 32 + cx0]);
                    a[mt][1] = __float_as_uint(As[(r + 8) * 32 + cx0]);
                    a[mt][2] = __float_as_uint(As[r * 32 + cx1]);
                    a[mt][3] = __float_as_uint(As[(r + 8) * 32 + cx1]);
                }
            }
            uint32_t b[4][2];
#pragma unroll
            for (int nt = 0; nt < 4; nt++) {
                int n = nBase + nt * 8 + l4;
                b[nt][0] = __float_as_uint(Bs[n * 32 + cx0]);
                b[nt][1] = __float_as_uint(Bs[n * 32 + cx1]);
            }
#pragma unroll
            for (int mt = 0; mt < 4; mt++)
#pragma unroll
                for (int nt = 0; nt < 4; nt++)
                    mma8(acc[mt][nt], a[mt], b[nt]);
        }
        if (WRXT) {
            // emit rna'd transpose of this 128x32 A tile: g_xT[b][d][n]
            const int b = (blockIdx.y * BM) / Nn;
            const int n0 = (blockIdx.y * BM) % Nn;
            const int d0 = kt * 32;
            float* xt = g_xT + (long)b * Dd * Nn + (long)d0 * Nn + n0;
#pragma unroll
            for (int dk = 0; dk < 32; dk++) {
                int kb = dk >> 2, lm = dk & 3;
                float v = rna_tf32(As[t * 32 + ((kb ^ (t & 7)) << 2) + lm]);
                xt[(long)dk * Nn + t] = v;
            }
        }
        __syncthreads();
    }

    // epilogue
    const int gn0 = blockIdx.x * BN + nBase;
#pragma unroll
    for (int mt = 0; mt < 4; mt++) {
        int gr0 = blockIdx.y * BM + mBase + mt * 16 + l4;
#pragma unroll
        for (int h = 0; h < 2; h++) {
            int gr = gr0 + 8 * h;
            float* crow = C + (long)gr * N + gn0;
            const float* pe = (EPI == 1) ? &g_pe[(gr & (Nn - 1)) * KDc + gn0] : (const float*)0;
#pragma unroll
            for (int nt = 0; nt < 4; nt++) {
                int gc = nt * 8 + 2 * lm4;
                float2 v;
                v.x = acc[mt][nt][2 * h + 0] * alpha;
                v.y = acc[mt][nt][2 * h + 1] * alpha;
                if (EPI == 1) { v.x += pe[gc]; v.y += pe[gc + 1]; }
                if (EPI == 1 || EPI == 3) { v.x = rna_tf32(v.x); v.y = rna_tf32(v.y); }
                *(float2*)&crow[gc] = v;
            }
        }
    }
}

// ---------------- fused zz GEMM + R reduction --------------------------------
// grid: x = 16 (r), y = 256 (96-row slabs = 32 groups each).
// Block computes tile T = gobj_slab(96x256) @ [Wq'[r] ; Wk'[r]]^T  (96x128),
// then R[r][bg][n*3+m] = sum_p T[g*3+n][p] * T[g*3+m][64+p].
__global__ __launch_bounds__(256, 2)
void zzR_kernel(const float* __restrict__ gobj, const float* __restrict__ wt2,
                float* __restrict__ R) {
    constexpr int BM = 96, STG = (BM + 128) * 32;   // 7168 floats/stage
    constexpr int EST = 130;                        // epilogue tile row stride
    extern __shared__ float sm[];
    const uint32_t smb = smem_u32(sm);
    const int t = threadIdx.x;
    const int wid = t >> 5, lane = t & 31;
    const int l4 = lane >> 2, lm4 = lane & 3;
    const int mBase = (wid >> 2) * 48;   // 2 warps along m (48 rows each)
    const int nBase = (wid & 3) * 32;    // 4 warps along n
    const int r = blockIdx.x;
    const int row0 = blockIdx.y * BM;

    const float* A  = gobj + (long)row0 * 256;
    const float* Bq = wt2 + (long)(r * 64) * 256;
    const float* Bk = wt2 + (long)(1024 + r * 64) * 256;

    auto load_stage = [&](int kt, int sb) {
        const int k0 = kt * 32;
        uint32_t ab = smb + sb * (STG * 4);
#pragma unroll
        for (int i = 0; i < 3; i++) {                 // A: 96*8/256 = 3
            int id = t + i * 256;
            int row = id >> 3, kb = id & 7;
            uint32_t dst = ab + (uint32_t)((row * 32 + ((kb ^ (row & 7)) << 2)) * 4);
            cpa16(dst, A + (long)row * 256 + k0 + kb * 4);
        }
        uint32_t bb = ab + BM * 32 * 4;
#pragma unroll
        for (int i = 0; i < 4; i++) {                 // B: 128*8/256 = 4
            int id = t + i * 256;
            int row = id >> 3, kb = id & 7;
            const float* src = (row < 64) ? (Bq + (long)row * 256)
                                          : (Bk + (long)(row - 64) * 256);
            uint32_t dst = bb + (uint32_t)((row * 32 + ((kb ^ (row & 7)) << 2)) * 4);
            cpa16(dst, src + k0 + kb * 4);
        }
        asm volatile("cp.async.commit_group;" ::: "memory");
    };

    float acc[3][4][4] = {};
    load_stage(0, 0);
    for (int kt = 0; kt < 8; kt++) {
        if (kt + 1 < 8) {
            load_stage(kt + 1, (kt + 1) & 1);
            asm volatile("cp.async.wait_group 1;" ::: "memory");
        } else {
            asm volatile("cp.async.wait_group 0;" ::: "memory");
        }
        __syncthreads();
        const float* As = sm + (kt & 1) * STG;
        const float* Bs = As + BM * 32;
#pragma unroll
        for (int ks = 0; ks < 4; ks++) {
            const int cx0 = lm4 + ((((2 * ks) ^ l4) & 7) << 2);
            const int cx1 = lm4 + ((((2 * ks + 1) ^ l4) & 7) << 2);
            uint32_t a[3][4];
#pragma unroll
            for (int mt = 0; mt < 3; mt++) {
                int rr = mBase + mt * 16 + l4;
                a[mt][0] = __float_as_uint(As[rr * 32 + cx0]);
                a[mt][1] = __float_as_uint(As[(rr + 8) * 32 + cx0]);
                a[mt][2] = __float_as_uint(As[rr * 32 + cx1]);
                a[mt][3] = __float_as_uint(As[(rr + 8) * 32 + cx1]);
            }
            uint32_t b[4][2];
#pragma unroll
            for (int nt = 0; nt < 4; nt++) {
                int n = nBase + nt * 8 + l4;
                b[nt][0] = __float_as_uint(Bs[n * 32 + cx0]);
                b[nt][1] = __float_as_uint(Bs[n * 32 + cx1]);
            }
#pragma unroll
            for (int mt = 0; mt < 3; mt++)
#pragma unroll
                for (int nt = 0; nt < 4; nt++)
                    mma8(acc[mt][nt], a[mt], b[nt]);
        }
        __syncthreads();
    }

    // stage the 96x128 tile to smem (aliases pipeline buffers; all reads done)
    float* ep = sm;
#pragma unroll
    for (int mt = 0; mt < 3; mt++) {
#pragma unroll
        for (int h = 0; h < 2; h++) {
            int row = mBase + mt * 16 + l4 + 8 * h;
#pragma unroll
            for (int nt = 0; nt < 4; nt++) {
                int col = nBase + nt * 8 + 2 * lm4;
                ep[row * EST + col]     = acc[mt][nt][2 * h + 0];
                ep[row * EST + col + 1] = acc[mt][nt][2 * h + 1];
            }
        }
    }
    __syncthreads();

    // R reduction: 32 groups x 9 pairs, dot over 64
    const long bg0 = row0 / 3;
    float* Rout = R + (long)r * NBG * 9;
    for (int w = t; w < 288; w += 256) {
        int gl = w / 9, pr = w % 9;
        int nn = pr / 3, mm = pr % 3;
        const float* ra = ep + (gl * 3 + nn) * EST;
        const float* rb = ep + (gl * 3 + mm) * EST + 64;
        float sum = 0.f;
#pragma unroll
        for (int p = 0; p < 64; p++) sum += ra[p] * rb[p];
        Rout[(bg0 + gl) * 9 + pr] = sum;
    }
}

// ---------------- R * Fsym contraction ---------------------------------------
__global__ __launch_bounds__(64)
void rfin_kernel(const float* __restrict__ R, float* __restrict__ out) {
    __shared__ float Rs[144];
    const int bg = blockIdx.x, t = threadIdx.x;
    for (int i = t; i < 144; i += 64) {
        int pr = i >> 4, r = i & 15;
        Rs[i] = R[(long)r * NBG * 9 + (long)bg * 9 + pr];
    }
    __syncthreads();
    const float* f = g_fsym + t * 144;
    float acc = 0.f;
#pragma unroll 16
    for (int i = 0; i < 144; i++) acc += Rs[i] * f[i];
    out[(long)bg * 64 + t] = acc;
}

// ---------------- precompute kernels -----------------------------------------
__global__ void pe_kernel() {
    int idx = blockIdx.x * blockDim.x + threadIdx.x;
    if (idx >= Nn * KDc) return;
    int n = idx >> 6, j = idx & 63;
    float e = (float)(j & ~1) / 64.0f;
    float angle = (float)n / powf(10000.0f, e);
    double a = (double)angle;
    g_pe[idx] = (j & 1) ? (float)cos(a) : (float)sin(a);
}

__global__ void fsym_kernel(const float* __restrict__ filters) {
    int idx = blockIdx.x * blockDim.x + threadIdx.x;
    if (idx >= 64 * 144) return;
    int f = idx / 144, rem = idx % 144;
    int n = rem / 48, m = (rem / 16) % 3, r = rem & 15;
    const int P[6][3] = {{0,1,2},{0,2,1},{1,0,2},{1,2,0},{2,0,1},{2,1,0}};
    float s = 0.f;
#pragma unroll
    for (int p = 0; p < 6; p++)
        s += filters[f * 144 + P[p][n] * 48 + P[p][m] * 16 + r];
    g_fsym[idx] = s * (1.0f / 6.0f);
}

__global__ void wt2_kernel(const float* __restrict__ Wq, const float* __restrict__ Wk) {
    int idx = blockIdx.x * blockDim.x + threadIdx.x;
    if (idx >= 2048 * 256) return;
    int c = idx >> 8, d = idx & 255;
    const float* W = (c < 1024) ? Wq : Wk;
    int cc = c & 1023, r = cc >> 6, p = cc & 63;
    g_wt2[idx] = rna_tf32(W[(r << 14) + (d << 6) + p]);
}

__global__ void smallprep_kernel(const float* __restrict__ wkmap, const float* __restrict__ qe) {
    int idx = blockIdx.x * blockDim.x + threadIdx.x;
    if (idx < 64 * 256) {
        int kd = idx >> 8, d = idx & 255;
        g_wkT[idx] = rna_tf32(wkmap[d * 64 + kd]);
    }
    if (idx < Qq * KDc) g_qer[idx] = rna_tf32(qe[idx]);
}

// row softmax over 1024 on S rows (b,q<192), output rna-rounded
__global__ __launch_bounds__(256)
void softmax_kernel() {
    __shared__ float red_m[8], red_s[8];
    int bq = blockIdx.x;
    int b = bq / Qq, q = bq % Qq;
    float* p = g_S + ((long)b * QP + q) * 1024;
    int t = threadIdx.x;
    float4 v = ((float4*)p)[t];
    float m = fmaxf(fmaxf(v.x, v.y), fmaxf(v.z, v.w));
#pragma unroll
    for (int o = 16; o; o >>= 1) m = fmaxf(m, __shfl_xor_sync(0xffffffffu, m, o));
    if ((t & 31) == 0) red_m[t >> 5] = m;
    __syncthreads();
    float bm = red_m[0];
#pragma unroll
    for (int i = 1; i < 8; i++) bm = fmaxf(bm, red_m[i]);
    v.x = expf(v.x - bm); v.y = expf(v.y - bm);
    v.z = expf(v.z - bm); v.w = expf(v.w - bm);
    float s = v.x + v.y + v.z + v.w;
#pragma unroll
    for (int o = 16; o; o >>= 1) s += __shfl_xor_sync(0xffffffffu, s, o);
    if ((t & 31) == 0) red_s[t >> 5] = s;
    __syncthreads();
    float tot = red_s[0];
#pragma unroll
    for (int i = 1; i < 8; i++) tot += red_s[i];
    float inv = 1.0f / tot;
    v.x = rna_tf32(v.x * inv); v.y = rna_tf32(v.y * inv);
    v.z = rna_tf32(v.z * inv); v.w = rna_tf32(v.w * inv);
    ((float4*)p)[t] = v;
}

// ---------------- launch -----------------------------------------------------
extern "C" void kernel_launch(void* const* d_in, const int* in_sizes, int n_in,
                              void* d_out, int out_size) {
    (void)in_sizes; (void)n_in; (void)out_size;
    const float* x       = (const float*)d_in[0];
    const float* filters = (const float*)d_in[1];
    const float* qe      = (const float*)d_in[2];
    const float* wkmap   = (const float*)d_in[3];
    const float* Wq      = (const float*)d_in[4];
    const float* Wk      = (const float*)d_in[5];
    float* out = (float*)d_out;

    float *pxT, *pk, *pS, *pg, *pR, *pwt2, *pwkT, *pqer;
    cudaGetSymbolAddress((void**)&pxT,  g_xT);
    cudaGetSymbolAddress((void**)&pk,   g_k);
    cudaGetSymbolAddress((void**)&pS,   g_S);
    cudaGetSymbolAddress((void**)&pg,   g_gobj);
    cudaGetSymbolAddress((void**)&pR,   g_R);
    cudaGetSymbolAddress((void**)&pwt2, g_wt2);
    cudaGetSymbolAddress((void**)&pwkT, g_wkT);
    cudaGetSymbolAddress((void**)&pqer, g_qer);

    const int SM_KP  = 2 * (128 + 64) * 32 * 4;   // 49152  (BM128,BN64)
    const int SM_SM  = 2 * (64 + 128) * 32 * 4;   // 49152  (BM64,BN128)
    const int SM_ZZR = 2 * (96 + 128) * 32 * 4;   // 57344
    cudaFuncSetAttribute((const void*)mma_gemm<128, 64, 1, true, true>,
                         cudaFuncAttributeMaxDynamicSharedMemorySize, SM_KP);
    cudaFuncSetAttribute((const void*)mma_gemm<64, 128, 2, false, false>,
                         cudaFuncAttributeMaxDynamicSharedMemorySize, SM_SM);
    cudaFuncSetAttribute((const void*)mma_gemm<64, 128, 3, false, false>,
                         cudaFuncAttributeMaxDynamicSharedMemorySize, SM_SM);
    cudaFuncSetAttribute((const void*)zzR_kernel,
                         cudaFuncAttributeMaxDynamicSharedMemorySize, SM_ZZR);

    pe_kernel<<<(Nn * KDc + 255) / 256, 256>>>();
    fsym_kernel<<<(64 * 144 + 255) / 256, 256>>>(filters);
    wt2_kernel<<<(2048 * 256 + 255) / 256, 256>>>(Wq, Wk);
    smallprep_kernel<<<(64 * 256 + 255) / 256, 256>>>(wkmap, qe);

    // k = rna(x @ wkT^T + PE), also emits xT : M=131072, N=64, K=256
    mma_gemm<128, 64, 1, true, true><<<dim3(1, 1024, 1), 128, SM_KP>>>(
        x, pwkT, pk, 256, 64, 0, 0, 0, 1.0f);

    // S[b] = 0.125 * qe @ k[b]^T : per b M=192 (BM=64), N=1024, K=64
    mma_gemm<64, 128, 2, false, false><<<dim3(8, 3, Bsz), 128, SM_SM>>>(
        pqer, pk, pS, 64, 1024,
        0, (long)Nn * KDc, (long)QP * Nn, 0.125f);

    softmax_kernel<<<Bsz * Qq, 256>>>();

    // gobj[b] = rna(S[b] @ xT[b]^T) : M=192 (BM=64), N=256, K=1024
    mma_gemm<64, 128, 3, false, false><<<dim3(2, 3, Bsz), 128, SM_SM>>>(
        pS, pxT, pg, 1024, 256,
        (long)QP * Nn, (long)Dd * Nn, (long)Qq * Dd, 1.0f);

    // fused zz GEMM + R : grid (r=16, 256 slabs of 96 rows)
    zzR_kernel<<<dim3(RELD, 256, 1), 256, SM_ZZR>>>(pg, pwt2, pR);

    // out[bg][f] = sum_i R[bg][i] * Fsym[f][i]
    rfin_kernel<<<NBG, 64>>>(pR, out);
}

// round 15
// speedup vs baseline: 3.7456x; 1.0244x over previous
#include <cuda_runtime.h>
#include <math.h>
#include <stdint.h>

// Problem dims
#define Bsz  128
#define Nn   1024
#define Dd   256
#define Gg   64
#define RELD 16
#define KDc  64
#define Qq   192

#define NBG  (Bsz * Gg)   // 8192

// ---------------- scratch (static device globals; zero-init, no allocs) -----
__device__ float g_pe[Nn * KDc];
__device__ float g_fsym[64 * 144];
__device__ float g_wt2[2048 * 256];               // (c=r*64+p, d) K-major, rna
__device__ float g_wkT[64 * 256];                 // (kd, d) K-major, rna
__device__ float g_qer[Qq * KDc];                 // rna copy of query_emb
__device__ float g_xT[(long)Bsz * Dd * Nn];       // x transposed (b,d,n), rna
__device__ float g_k[(long)Bsz * Nn * KDc];       // keys (rna'd in epilogue)
__device__ float g_gobj[(long)Bsz * Qq * Dd];     // (b*192+q, d), rna
__device__ float g_R[(long)RELD * NBG * 9];       // R[r][bg][n*3+m]

// ---------------- helpers ----------------------------------------------------
__device__ __forceinline__ uint32_t smem_u32(const void* p) {
    uint32_t a;
    asm("{ .reg .u64 t; cvta.to.shared.u64 t, %1; cvt.u32.u64 %0, t; }"
        : "=r"(a) : "l"(p));
    return a;
}
__device__ __forceinline__ float rna_tf32(float x) {
    uint32_t u;
    asm("cvt.rna.tf32.f32 %0, %1;" : "=r"(u) : "f"(x));
    return __uint_as_float(u);
}
__device__ __forceinline__ uint32_t rna_bits(float x) {
    uint32_t u;
    asm("cvt.rna.tf32.f32 %0, %1;" : "=r"(u) : "f"(x));
    return u;
}
__device__ __forceinline__ void cpa16(uint32_t dst, const void* src) {
    asm volatile("cp.async.ca.shared.global [%0], [%1], 16;"
                 :: "r"(dst), "l"(src) : "memory");
}
__device__ __forceinline__ void mma8(float* c, const uint32_t* a, const uint32_t* b) {
    asm volatile(
        "mma.sync.aligned.m16n8k8.row.col.f32.tf32.tf32.f32 "
        "{%0,%1,%2,%3}, {%4,%5,%6,%7}, {%8,%9}, {%0,%1,%2,%3};"
        : "+f"(c[0]), "+f"(c[1]), "+f"(c[2]), "+f"(c[3])
        : "r"(a[0]), "r"(a[1]), "r"(a[2]), "r"(a[3]), "r"(b[0]), "r"(b[1]));
}

// ---------------- tf32 mma.sync NT GEMM (k-projection) -----------------------
template<int BM, int BN, int EPI, bool RNAA, bool WRXT>
__global__ __launch_bounds__((BM / 64) * (BN / 32) * 32, 2)
void mma_gemm(const float* __restrict__ A, const float* __restrict__ B,
              float* __restrict__ C, int K, int N,
              long sA, long sB, long sC, float alpha) {
    constexpr int THREADS = (BM / 64) * (BN / 32) * 32;
    constexpr int WN = BN / 32;
    constexpr int STG = (BM + BN) * 32;
    constexpr int CA = BM * 8 / THREADS;
    constexpr int CB = BN * 8 / THREADS;
    extern __shared__ float sm[];
    const uint32_t smb = smem_u32(sm);

    const int t = threadIdx.x;
    const int wid = t >> 5, lane = t & 31;
    const int l4 = lane >> 2, lm4 = lane & 3;
    const int mBase = (wid / WN) * 64;
    const int nBase = (wid % WN) * 32;

    A += (long)blockIdx.z * sA + (long)(blockIdx.y * BM) * K;
    B += (long)blockIdx.z * sB + (long)(blockIdx.x * BN) * K;
    C += (long)blockIdx.z * sC;

    auto load_stage = [&](int kt, int sb) {
        const int k0 = kt * 32;
        uint32_t ab = smb + sb * (STG * 4);
#pragma unroll
        for (int i = 0; i < CA; i++) {
            int id = t + i * THREADS;
            int row = id >> 3, kb = id & 7;
            uint32_t dst = ab + (uint32_t)((row * 32 + ((kb ^ (row & 7)) << 2)) * 4);
            cpa16(dst, A + (long)row * K + k0 + kb * 4);
        }
        uint32_t bb = ab + BM * 32 * 4;
#pragma unroll
        for (int i = 0; i < CB; i++) {
            int id = t + i * THREADS;
            int row = id >> 3, kb = id & 7;
            uint32_t dst = bb + (uint32_t)((row * 32 + ((kb ^ (row & 7)) << 2)) * 4);
            cpa16(dst, B + (long)row * K + k0 + kb * 4);
        }
        asm volatile("cp.async.commit_group;" ::: "memory");
    };

    float acc[4][4][4] = {};
    const int KT = K / 32;
    load_stage(0, 0);

    for (int kt = 0; kt < KT; kt++) {
        if (kt + 1 < KT) {
            load_stage(kt + 1, (kt + 1) & 1);
            asm volatile("cp.async.wait_group 1;" ::: "memory");
        } else {
            asm volatile("cp.async.wait_group 0;" ::: "memory");
        }
        __syncthreads();
        const float* As = sm + (kt & 1) * STG;
        const float* Bs = As + BM * 32;
#pragma unroll
        for (int ks = 0; ks < 4; ks++) {
            const int cx0 = lm4 + ((((2 * ks) ^ l4) & 7) << 2);
            const int cx1 = lm4 + ((((2 * ks + 1) ^ l4) & 7) << 2);
            uint32_t a[4][4];
#pragma unroll
            for (int mt = 0; mt < 4; mt++) {
                int r = mBase + mt * 16 + l4;
                if (RNAA) {
                    a[mt][0] = rna_bits(As[r * 32 + cx0]);
                    a[mt][1] = rna_bits(As[(r + 8) * 32 + cx0]);
                    a[mt][2] = rna_bits(As[r * 32 + cx1]);
                    a[mt][3] = rna_bits(As[(r + 8) * 32 + cx1]);
                } else {
                    a[mt][0] = __float_as_uint(As[r * 32 + cx0]);
                    a[mt][1] = __float_as_uint(As[(r + 8) * 32 + cx0]);
                    a[mt][2] = __float_as_uint(As[r * 32 + cx1]);
                    a[mt][3] = __float_as_uint(As[(r + 8) * 32 + cx1]);
                }
            }
            uint32_t b[4][2];
#pragma unroll
            for (int nt = 0; nt < 4; nt++) {
                int n = nBase + nt * 8 + l4;
                b[nt][0] = __float_as_uint(Bs[n * 32 + cx0]);
                b[nt][1] = __float_as_uint(Bs[n * 32 + cx1]);
            }
#pragma unroll
            for (int mt = 0; mt < 4; mt++)
#pragma unroll
                for (int nt = 0; nt < 4; nt++)
                    mma8(acc[mt][nt], a[mt], b[nt]);
        }
        if (WRXT) {
            const int b = (blockIdx.y * BM) / Nn;
            const int n0 = (blockIdx.y * BM) % Nn;
            const int d0 = kt * 32;
            float* xt = g_xT + (long)b * Dd * Nn + (long)d0 * Nn + n0;
#pragma unroll
            for (int dk = 0; dk < 32; dk++) {
                int kb = dk >> 2, lm = dk & 3;
                float v = rna_tf32(As[t * 32 + ((kb ^ (t & 7)) << 2) + lm]);
                xt[(long)dk * Nn + t] = v;
            }
        }
        __syncthreads();
    }

    const int gn0 = blockIdx.x * BN + nBase;
#pragma unroll
    for (int mt = 0; mt < 4; mt++) {
        int gr0 = blockIdx.y * BM + mBase + mt * 16 + l4;
#pragma unroll
        for (int h = 0; h < 2; h++) {
            int gr = gr0 + 8 * h;
            float* crow = C + (long)gr * N + gn0;
            const float* pe = (EPI == 1) ? &g_pe[(gr & (Nn - 1)) * KDc + gn0] : (const float*)0;
#pragma unroll
            for (int nt = 0; nt < 4; nt++) {
                int gc = nt * 8 + 2 * lm4;
                float2 v;
                v.x = acc[mt][nt][2 * h + 0] * alpha;
                v.y = acc[mt][nt][2 * h + 1] * alpha;
                if (EPI == 1) { v.x += pe[gc]; v.y += pe[gc + 1]; }
                if (EPI == 1 || EPI == 3) { v.x = rna_tf32(v.x); v.y = rna_tf32(v.y); }
                *(float2*)&crow[gc] = v;
            }
        }
    }
}

// ---------------- fused attention: logits + online softmax + gobj ------------
// Block = (qt in 0..2, b). 256 threads, 8 warps: mw = wid>>2 (2 row-warps of 32),
// nw = wid&3 (logits: 16-col slice; gobj: 64-d slice). 16 chunks of 64 n.
// smem floats: qe[4096] | P[4096] | k[2][4096] | x[2][16384] | pmax[256] |
//              psum[256] | Mrun[64] | Lrun[64]
__global__ __launch_bounds__(256, 1)
void attn_kernel(const float* __restrict__ kg, const float* __restrict__ xT,
                 const float* __restrict__ qe, float* __restrict__ gobj) {
    extern __shared__ float sm[];
    float* Pt   = sm + 4096;
    float* pmax = sm + 49152;
    float* psum = sm + 49408;
    float* Mrun = sm + 49664;
    float* Lrun = sm + 49728;
    const uint32_t smb = smem_u32(sm);
    const int t = threadIdx.x, wid = t >> 5, lane = t & 31;
    const int l4 = lane >> 2, lm4 = lane & 3;
    const int mw = wid >> 2, nw = wid & 3;
    const int qt = blockIdx.x, b = blockIdx.y;

    if (t < 64) { Mrun[t] = -1e30f; Lrun[t] = 0.f; }

    const float* kbase = kg + (long)b * Nn * KDc;
    const float* xbase = xT + (long)b * Dd * Nn;
    const float* qbase = qe + qt * 64 * KDc;

    // qe tile (group 0): 64 x 64, two 32-col swizzled panels
#pragma unroll
    for (int i = 0; i < 4; i++) {
        int id = t + i * 256; int row = id >> 4, f4 = id & 15, kp = f4 >> 3, kb = f4 & 7;
        uint32_t dst = smb + (uint32_t)((kp * 2048 + row * 32 + ((kb ^ (row & 7)) << 2)) * 4);
        cpa16(dst, qbase + row * 64 + f4 * 4);
    }
    asm volatile("cp.async.commit_group;" ::: "memory");

    auto load_chunk = [&](int ch, int sb) {
#pragma unroll
        for (int i = 0; i < 4; i++) {        // k: 64 x 64
            int id = t + i * 256; int row = id >> 4, f4 = id & 15, kp = f4 >> 3, kb = f4 & 7;
            uint32_t dst = smb + (uint32_t)((8192 + sb * 4096 + kp * 2048 +
                                             row * 32 + ((kb ^ (row & 7)) << 2)) * 4);
            cpa16(dst, kbase + (long)(ch * 64 + row) * 64 + f4 * 4);
        }
#pragma unroll
        for (int i = 0; i < 16; i++) {       // xT: 256 x 64
            int id = t + i * 256; int row = id >> 4, f4 = id & 15, kp = f4 >> 3, kb = f4 & 7;
            uint32_t dst = smb + (uint32_t)((16384 + sb * 16384 + kp * 8192 +
                                             row * 32 + ((kb ^ (row & 7)) << 2)) * 4);
            cpa16(dst, xbase + (long)row * 1024 + ch * 64 + f4 * 4);
        }
        asm volatile("cp.async.commit_group;" ::: "memory");
    };

    float accg[2][8][4] = {};
    load_chunk(0, 0);
    __syncthreads();

    for (int ch = 0; ch < 16; ch++) {
        const int sb = ch & 1;
        if (ch + 1 < 16) {
            load_chunk(ch + 1, sb ^ 1);
            asm volatile("cp.async.wait_group 1;" ::: "memory");
        } else {
            asm volatile("cp.async.wait_group 0;" ::: "memory");
        }
        __syncthreads();

        // ---- logits mma: 64x64, K=64 ----
        float accl[2][2][4] = {};
#pragma unroll
        for (int kp = 0; kp < 2; kp++) {
            const float* Asm = sm + kp * 2048;
            const float* Bsm = sm + 8192 + sb * 4096 + kp * 2048;
#pragma unroll
            for (int ks = 0; ks < 4; ks++) {
                int cx0 = lm4 + ((((2 * ks) ^ l4) & 7) << 2);
                int cx1 = lm4 + ((((2 * ks + 1) ^ l4) & 7) << 2);
                uint32_t a[2][4];
#pragma unroll
                for (int mt = 0; mt < 2; mt++) {
                    int r = mw * 32 + mt * 16 + l4;
                    a[mt][0] = __float_as_uint(Asm[r * 32 + cx0]);
                    a[mt][1] = __float_as_uint(Asm[(r + 8) * 32 + cx0]);
                    a[mt][2] = __float_as_uint(Asm[r * 32 + cx1]);
                    a[mt][3] = __float_as_uint(Asm[(r + 8) * 32 + cx1]);
                }
                uint32_t bb[2][2];
#pragma unroll
                for (int nt = 0; nt < 2; nt++) {
                    int n = nw * 16 + nt * 8 + l4;
                    bb[nt][0] = __float_as_uint(Bsm[n * 32 + cx0]);
                    bb[nt][1] = __float_as_uint(Bsm[n * 32 + cx1]);
                }
#pragma unroll
                for (int mt = 0; mt < 2; mt++)
#pragma unroll
                    for (int nt = 0; nt < 2; nt++)
                        mma8(accl[mt][nt], a[mt], bb[nt]);
            }
        }
#pragma unroll
        for (int mt = 0; mt < 2; mt++)
#pragma unroll
            for (int nt = 0; nt < 2; nt++)
#pragma unroll
                for (int c = 0; c < 4; c++) accl[mt][nt][c] *= 0.125f;

        // ---- chunk row-max partials ----
#pragma unroll
        for (int mt = 0; mt < 2; mt++)
#pragma unroll
            for (int h = 0; h < 2; h++) {
                float m = fmaxf(fmaxf(accl[mt][0][2 * h], accl[mt][0][2 * h + 1]),
                                fmaxf(accl[mt][1][2 * h], accl[mt][1][2 * h + 1]));
                m = fmaxf(m, __shfl_xor_sync(0xffffffffu, m, 1));
                m = fmaxf(m, __shfl_xor_sync(0xffffffffu, m, 2));
                if (lm4 == 0) pmax[(mw * 32 + mt * 16 + l4 + 8 * h) * 4 + nw] = m;
            }
        __syncthreads();

        // ---- P = exp(l - Mnew), rescale accg, partial sums, stage P ----
        float Mn_[2][2], f_[2][2];
#pragma unroll
        for (int mt = 0; mt < 2; mt++)
#pragma unroll
            for (int h = 0; h < 2; h++) {
                int row = mw * 32 + mt * 16 + l4 + 8 * h;
                float Mo = Mrun[row];
                float Mn = fmaxf(fmaxf(fmaxf(pmax[row * 4], pmax[row * 4 + 1]),
                                       fmaxf(pmax[row * 4 + 2], pmax[row * 4 + 3])), Mo);
                Mn_[mt][h] = Mn; f_[mt][h] = __expf(Mo - Mn);
            }
#pragma unroll
        for (int mt = 0; mt < 2; mt++)
#pragma unroll
            for (int h = 0; h < 2; h++) {
                float s = 0.f;
#pragma unroll
                for (int nt = 0; nt < 2; nt++) {
                    float p0 = __expf(accl[mt][nt][2 * h]     - Mn_[mt][h]);
                    float p1 = __expf(accl[mt][nt][2 * h + 1] - Mn_[mt][h]);
                    s += p0 + p1;
                    accl[mt][nt][2 * h] = p0; accl[mt][nt][2 * h + 1] = p1;
                }
                s += __shfl_xor_sync(0xffffffffu, s, 1);
                s += __shfl_xor_sync(0xffffffffu, s, 2);
                if (lm4 == 0) psum[(mw * 32 + mt * 16 + l4 + 8 * h) * 4 + nw] = s;
#pragma unroll
                for (int nt = 0; nt < 8; nt++) {
                    accg[mt][nt][2 * h]     *= f_[mt][h];
                    accg[mt][nt][2 * h + 1] *= f_[mt][h];
                }
            }
#pragma unroll
        for (int mt = 0; mt < 2; mt++)
#pragma unroll
            for (int h = 0; h < 2; h++) {
                int row = mw * 32 + mt * 16 + l4 + 8 * h;
#pragma unroll
                for (int nt = 0; nt < 2; nt++) {
                    int col = nw * 16 + nt * 8 + 2 * lm4;
                    int kp = col >> 5, kc = col & 31, kb = kc >> 2, lm = kc & 3;
                    float2 v;
                    v.x = rna_tf32(accl[mt][nt][2 * h]);
                    v.y = rna_tf32(accl[mt][nt][2 * h + 1]);
                    *(float2*)&Pt[kp * 2048 + row * 32 + ((kb ^ (row & 7)) << 2) + lm] = v;
                }
            }
        __syncthreads();

        // ---- update running stats (one thread per row) ----
        if (t < 64) {
            float Mo = Mrun[t];
            float Mn = fmaxf(fmaxf(fmaxf(pmax[t * 4], pmax[t * 4 + 1]),
                                   fmaxf(pmax[t * 4 + 2], pmax[t * 4 + 3])), Mo);
            Lrun[t] = Lrun[t] * __expf(Mo - Mn) +
                      (psum[t * 4] + psum[t * 4 + 1] + psum[t * 4 + 2] + psum[t * 4 + 3]);
            Mrun[t] = Mn;
        }

        // ---- gobj mma: accg += P(64xK64) @ x(256xK64)^T ----
#pragma unroll
        for (int kp = 0; kp < 2; kp++) {
            const float* Asm = Pt + kp * 2048;
            const float* Bsm = sm + 16384 + sb * 16384 + kp * 8192;
#pragma unroll
            for (int ks = 0; ks < 4; ks++) {
                int cx0 = lm4 + ((((2 * ks) ^ l4) & 7) << 2);
                int cx1 = lm4 + ((((2 * ks + 1) ^ l4) & 7) << 2);
                uint32_t a[2][4];
#pragma unroll
                for (int mt = 0; mt < 2; mt++) {
                    int r = mw * 32 + mt * 16 + l4;
                    a[mt][0] = __float_as_uint(Asm[r * 32 + cx0]);
                    a[mt][1] = __float_as_uint(Asm[(r + 8) * 32 + cx0]);
                    a[mt][2] = __float_as_uint(Asm[r * 32 + cx1]);
                    a[mt][3] = __float_as_uint(Asm[(r + 8) * 32 + cx1]);
                }
#pragma unroll
                for (int nt = 0; nt < 8; nt++) {
                    int n = nw * 64 + nt * 8 + l4;
                    uint32_t bb[2];
                    bb[0] = __float_as_uint(Bsm[n * 32 + cx0]);
                    bb[1] = __float_as_uint(Bsm[n * 32 + cx1]);
#pragma unroll
                    for (int mt = 0; mt < 2; mt++) mma8(accg[mt][nt], a[mt], bb);
                }
            }
        }
        __syncthreads();
    }

    // ---- finalize: divide by L, rna, store ----
#pragma unroll
    for (int mt = 0; mt < 2; mt++)
#pragma unroll
        for (int h = 0; h < 2; h++) {
            int row = mw * 32 + mt * 16 + l4 + 8 * h;
            float inv = 1.0f / Lrun[row];
            long base = ((long)b * Qq + qt * 64 + row) * 256 + nw * 64;
#pragma unroll
            for (int nt = 0; nt < 8; nt++) {
                float2 v;
                v.x = rna_tf32(accg[mt][nt][2 * h]     * inv);
                v.y = rna_tf32(accg[mt][nt][2 * h + 1] * inv);
                *(float2*)&gobj[base + nt * 8 + 2 * lm4] = v;
            }
        }
}

// ---------------- fused zz GEMM + R reduction --------------------------------
__global__ __launch_bounds__(256, 2)
void zzR_kernel(const float* __restrict__ gobj, const float* __restrict__ wt2,
                float* __restrict__ R) {
    constexpr int BM = 96, STG = (BM + 128) * 32;
    constexpr int EST = 130;
    extern __shared__ float sm[];
    const uint32_t smb = smem_u32(sm);
    const int t = threadIdx.x;
    const int wid = t >> 5, lane = t & 31;
    const int l4 = lane >> 2, lm4 = lane & 3;
    const int mBase = (wid >> 2) * 48;
    const int nBase = (wid & 3) * 32;
    const int r = blockIdx.x;
    const int row0 = blockIdx.y * BM;

    const float* A  = gobj + (long)row0 * 256;
    const float* Bq = wt2 + (long)(r * 64) * 256;
    const float* Bk = wt2 + (long)(1024 + r * 64) * 256;

    auto load_stage = [&](int kt, int sb) {
        const int k0 = kt * 32;
        uint32_t ab = smb + sb * (STG * 4);
#pragma unroll
        for (int i = 0; i < 3; i++) {
            int id = t + i * 256;
            int row = id >> 3, kb = id & 7;
            uint32_t dst = ab + (uint32_t)((row * 32 + ((kb ^ (row & 7)) << 2)) * 4);
            cpa16(dst, A + (long)row * 256 + k0 + kb * 4);
        }
        uint32_t bb = ab + BM * 32 * 4;
#pragma unroll
        for (int i = 0; i < 4; i++) {
            int id = t + i * 256;
            int row = id >> 3, kb = id & 7;
            const float* src = (row < 64) ? (Bq + (long)row * 256)
                                          : (Bk + (long)(row - 64) * 256);
            uint32_t dst = bb + (uint32_t)((row * 32 + ((kb ^ (row & 7)) << 2)) * 4);
            cpa16(dst, src + k0 + kb * 4);
        }
        asm volatile("cp.async.commit_group;" ::: "memory");
    };

    float acc[3][4][4] = {};
    load_stage(0, 0);
    for (int kt = 0; kt < 8; kt++) {
        if (kt + 1 < 8) {
            load_stage(kt + 1, (kt + 1) & 1);
            asm volatile("cp.async.wait_group 1;" ::: "memory");
        } else {
            asm volatile("cp.async.wait_group 0;" ::: "memory");
        }
        __syncthreads();
        const float* As = sm + (kt & 1) * STG;
        const float* Bs = As + BM * 32;
#pragma unroll
        for (int ks = 0; ks < 4; ks++) {
            const int cx0 = lm4 + ((((2 * ks) ^ l4) & 7) << 2);
            const int cx1 = lm4 + ((((2 * ks + 1) ^ l4) & 7) << 2);
            uint32_t a[3][4];
#pragma unroll
            for (int mt = 0; mt < 3; mt++) {
                int rr = mBase + mt * 16 + l4;
                a[mt][0] = __float_as_uint(As[rr * 32 + cx0]);
                a[mt][1] = __float_as_uint(As[(rr + 8) * 32 + cx0]);
                a[mt][2] = __float_as_uint(As[rr * 32 + cx1]);
                a[mt][3] = __float_as_uint(As[(rr + 8) * 32 + cx1]);
            }
            uint32_t b[4][2];
#pragma unroll
            for (int nt = 0; nt < 4; nt++) {
                int n = nBase + nt * 8 + l4;
                b[nt][0] = __float_as_uint(Bs[n * 32 + cx0]);
                b[nt][1] = __float_as_uint(Bs[n * 32 + cx1]);
            }
#pragma unroll
            for (int mt = 0; mt < 3; mt++)
#pragma unroll
                for (int nt = 0; nt < 4; nt++)
                    mma8(acc[mt][nt], a[mt], b[nt]);
        }
        __syncthreads();
    }

    float* ep = sm;
#pragma unroll
    for (int mt = 0; mt < 3; mt++) {
#pragma unroll
        for (int h = 0; h < 2; h++) {
            int row = mBase + mt * 16 + l4 + 8 * h;
#pragma unroll
            for (int nt = 0; nt < 4; nt++) {
                int col = nBase + nt * 8 + 2 * lm4;
                ep[row * EST + col]     = acc[mt][nt][2 * h + 0];
                ep[row * EST + col + 1] = acc[mt][nt][2 * h + 1];
            }
        }
    }
    __syncthreads();

    const long bg0 = row0 / 3;
    float* Rout = R + (long)r * NBG * 9;
    for (int w = t; w < 288; w += 256) {
        int gl = w / 9, pr = w % 9;
        int nn = pr / 3, mm = pr % 3;
        const float* ra = ep + (gl * 3 + nn) * EST;
        const float* rb = ep + (gl * 3 + mm) * EST + 64;
        float sum = 0.f;
#pragma unroll
        for (int p = 0; p < 64; p++) sum += ra[p] * rb[p];
        Rout[(bg0 + gl) * 9 + pr] = sum;
    }
}

// ---------------- R * Fsym contraction ---------------------------------------
__global__ __launch_bounds__(64)
void rfin_kernel(const float* __restrict__ R, float* __restrict__ out) {
    __shared__ float Rs[144];
    const int bg = blockIdx.x, t = threadIdx.x;
    for (int i = t; i < 144; i += 64) {
        int pr = i >> 4, r = i & 15;
        Rs[i] = R[(long)r * NBG * 9 + (long)bg * 9 + pr];
    }
    __syncthreads();
    const float* f = g_fsym + t * 144;
    float acc = 0.f;
#pragma unroll 16
    for (int i = 0; i < 144; i++) acc += Rs[i] * f[i];
    out[(long)bg * 64 + t] = acc;
}

// ---------------- precompute kernels -----------------------------------------
__global__ void pe_kernel() {
    int idx = blockIdx.x * blockDim.x + threadIdx.x;
    if (idx >= Nn * KDc) return;
    int n = idx >> 6, j = idx & 63;
    float e = (float)(j & ~1) / 64.0f;
    float angle = (float)n / powf(10000.0f, e);
    double a = (double)angle;
    g_pe[idx] = (j & 1) ? (float)cos(a) : (float)sin(a);
}

__global__ void fsym_kernel(const float* __restrict__ filters) {
    int idx = blockIdx.x * blockDim.x + threadIdx.x;
    if (idx >= 64 * 144) return;
    int f = idx / 144, rem = idx % 144;
    int n = rem / 48, m = (rem / 16) % 3, r = rem & 15;
    const int P[6][3] = {{0,1,2},{0,2,1},{1,0,2},{1,2,0},{2,0,1},{2,1,0}};
    float s = 0.f;
#pragma unroll
    for (int p = 0; p < 6; p++)
        s += filters[f * 144 + P[p][n] * 48 + P[p][m] * 16 + r];
    g_fsym[idx] = s * (1.0f / 6.0f);
}

__global__ void wt2_kernel(const float* __restrict__ Wq, const float* __restrict__ Wk) {
    int idx = blockIdx.x * blockDim.x + threadIdx.x;
    if (idx >= 2048 * 256) return;
    int c = idx >> 8, d = idx & 255;
    const float* W = (c < 1024) ? Wq : Wk;
    int cc = c & 1023, r = cc >> 6, p = cc & 63;
    g_wt2[idx] = rna_tf32(W[(r << 14) + (d << 6) + p]);
}

__global__ void smallprep_kernel(const float* __restrict__ wkmap, const float* __restrict__ qe) {
    int idx = blockIdx.x * blockDim.x + threadIdx.x;
    if (idx < 64 * 256) {
        int kd = idx >> 8, d = idx & 255;
        g_wkT[idx] = rna_tf32(wkmap[d * 64 + kd]);
    }
    if (idx < Qq * KDc) g_qer[idx] = rna_tf32(qe[idx]);
}

// ---------------- launch -----------------------------------------------------
extern "C" void kernel_launch(void* const* d_in, const int* in_sizes, int n_in,
                              void* d_out, int out_size) {
    (void)in_sizes; (void)n_in; (void)out_size;
    const float* x       = (const float*)d_in[0];
    const float* filters = (const float*)d_in[1];
    const float* qe      = (const float*)d_in[2];
    const float* wkmap   = (const float*)d_in[3];
    const float* Wq      = (const float*)d_in[4];
    const float* Wk      = (const float*)d_in[5];
    float* out = (float*)d_out;

    float *pxT, *pk, *pg, *pR, *pwt2, *pwkT, *pqer;
    cudaGetSymbolAddress((void**)&pxT,  g_xT);
    cudaGetSymbolAddress((void**)&pk,   g_k);
    cudaGetSymbolAddress((void**)&pg,   g_gobj);
    cudaGetSymbolAddress((void**)&pR,   g_R);
    cudaGetSymbolAddress((void**)&pwt2, g_wt2);
    cudaGetSymbolAddress((void**)&pwkT, g_wkT);
    cudaGetSymbolAddress((void**)&pqer, g_qer);

    const int SM_KP   = 2 * (128 + 64) * 32 * 4;   // 49152
    const int SM_ZZR  = 2 * (96 + 128) * 32 * 4;   // 57344
    const int SM_ATTN = 49792 * 4;                 // 199168
    cudaFuncSetAttribute((const void*)mma_gemm<128, 64, 1, true, true>,
                         cudaFuncAttributeMaxDynamicSharedMemorySize, SM_KP);
    cudaFuncSetAttribute((const void*)attn_kernel,
                         cudaFuncAttributeMaxDynamicSharedMemorySize, SM_ATTN);
    cudaFuncSetAttribute((const void*)zzR_kernel,
                         cudaFuncAttributeMaxDynamicSharedMemorySize, SM_ZZR);

    pe_kernel<<<(Nn * KDc + 255) / 256, 256>>>();
    fsym_kernel<<<(64 * 144 + 255) / 256, 256>>>(filters);
    wt2_kernel<<<(2048 * 256 + 255) / 256, 256>>>(Wq, Wk);
    smallprep_kernel<<<(64 * 256 + 255) / 256, 256>>>(wkmap, qe);

    // k = rna(x @ wkT^T + PE), also emits xT : M=131072, N=64, K=256
    mma_gemm<128, 64, 1, true, true><<<dim3(1, 1024, 1), 128, SM_KP>>>(
        x, pwkT, pk, 256, 64, 0, 0, 0, 1.0f);

    // fused logits + softmax + gobj : grid (3 q-tiles, 128 b)
    attn_kernel<<<dim3(3, Bsz), 256, SM_ATTN>>>(pk, pxT, pqer, pg);

    // fused zz GEMM + R : grid (r=16, 256 slabs of 96 rows)
    zzR_kernel<<<dim3(RELD, 256, 1), 256, SM_ZZR>>>(pg, pwt2, pR);

    // out[bg][f] = sum_i R[bg][i] * Fsym[f][i]
    rfin_kernel<<<NBG, 64>>>(pR, out);
}